// round 8
// baseline (speedup 1.0000x reference)
#include <cuda_runtime.h>
#include <cuda_bf16.h>
#include <cstdint>

#define HD   128
#define RR   8
#define NMAX 50000
#define EMAX 500000
#define NK   (NMAX * RR)        // 400000 bins
#define KTOT (HD + RR * HD)     // 1152
#define NCHUNK 36               // 1152 / 32
#define AST  40                 // smem row stride (bf16 elems): 32 + 8 pad

// ---------------- scratch (static device globals; no allocation) ----------------
__device__ __nv_bfloat16 g_aggh[(size_t)NMAX * RR * HD];  // [N,8,128] hi
__device__ __nv_bfloat16 g_aggl[(size_t)NMAX * RR * HD];  // [N,8,128] lo
__device__ int   g_cnt[NK];
__device__ int   g_off[NK];
__device__ int   g_cur[NK];
__device__ int   g_bsum[512];
__device__ int   g_esrc[EMAX];
__device__ __nv_bfloat16 g_xh[(size_t)NMAX * HD],  g_xl[(size_t)NMAX * HD];
__device__ __nv_bfloat16 g_h1h[(size_t)NMAX * HD], g_h1l[(size_t)NMAX * HD];
__device__ __nv_bfloat16 g_h2h[(size_t)NMAX * HD], g_h2l[(size_t)NMAX * HD];
__device__ __nv_bfloat16 g_Bh1[128 * KTOT];         // B^T hi/lo: [n][k]
__device__ __nv_bfloat16 g_Bl1[128 * KTOT];
__device__ __nv_bfloat16 g_Bh2[128 * KTOT];
__device__ __nv_bfloat16 g_Bl2[128 * KTOT];

// ---------------- helpers ----------------
__device__ __forceinline__ uint32_t smem_u32(const void* p) {
    return (uint32_t)__cvta_generic_to_shared(p);
}
__device__ __forceinline__ void ldsm_x4(uint32_t* r, uint32_t addr) {
    asm volatile("ldmatrix.sync.aligned.m8n8.x4.shared.b16 {%0,%1,%2,%3}, [%4];"
                 : "=r"(r[0]), "=r"(r[1]), "=r"(r[2]), "=r"(r[3]) : "r"(addr));
}
__device__ __forceinline__ void mma16816(float* d, const uint32_t* a, const uint32_t* b) {
    asm volatile(
        "mma.sync.aligned.m16n8k16.row.col.f32.bf16.bf16.f32 "
        "{%0,%1,%2,%3}, {%4,%5,%6,%7}, {%8,%9}, {%0,%1,%2,%3};"
        : "+f"(d[0]), "+f"(d[1]), "+f"(d[2]), "+f"(d[3])
        : "r"(a[0]), "r"(a[1]), "r"(a[2]), "r"(a[3]), "r"(b[0]), "r"(b[1]));
}
__device__ __forceinline__ void cp_async16(uint32_t smem_dst, const void* gptr) {
    asm volatile("cp.async.cg.shared.global [%0], [%1], 16;"
                 :: "r"(smem_dst), "l"(gptr));
}
__device__ __forceinline__ void cp_commit() { asm volatile("cp.async.commit_group;"); }
__device__ __forceinline__ void cp_wait0()  { asm volatile("cp.async.wait_group 0;"); }

__device__ __forceinline__ void split_bf16(float v, __nv_bfloat16& h, __nv_bfloat16& l) {
    h = __float2bfloat16(v);
    l = __float2bfloat16(v - __bfloat162float(h));
}

// ---------------- CSR build: count -> scan -> place ----------------
__global__ void count_kernel(const int* __restrict__ dst, const int* __restrict__ et,
                             int* cnt, int E) {
    int e = blockIdx.x * blockDim.x + threadIdx.x;
    if (e < E) atomicAdd(&cnt[dst[e] * RR + et[e]], 1);
}

__global__ void scan1_kernel(const int* __restrict__ cnt, int* bsum, int nk) {
    __shared__ int sh[256];
    int b = blockIdx.x, t = threadIdx.x;
    int base = b * 1024 + t * 4;
    int s = 0;
    if (base + 3 < nk) {
        int4 v = *(const int4*)(cnt + base);
        s = v.x + v.y + v.z + v.w;
    } else {
        for (int j = 0; j < 4; j++) if (base + j < nk) s += cnt[base + j];
    }
    sh[t] = s; __syncthreads();
    for (int o = 128; o; o >>= 1) { if (t < o) sh[t] += sh[t + o]; __syncthreads(); }
    if (t == 0) bsum[b] = sh[0];
}

__global__ void scan2_kernel(int* bsum, int nb) {
    __shared__ int sh[512];
    int t = threadIdx.x;
    int v = (t < nb) ? bsum[t] : 0;
    sh[t] = v; __syncthreads();
    for (int o = 1; o < 512; o <<= 1) {
        int add = (t >= o) ? sh[t - o] : 0;
        __syncthreads();
        sh[t] += add;
        __syncthreads();
    }
    if (t < nb) bsum[t] = sh[t] - v;   // exclusive
}

__global__ void scan3_kernel(const int* __restrict__ cnt, const int* __restrict__ bsum,
                             int* off, int* cur, int nk) {
    __shared__ int sh[256];
    int b = blockIdx.x, t = threadIdx.x;
    int base = b * 1024 + t * 4;
    int v[4] = {0, 0, 0, 0};
    if (base + 3 < nk) {
        int4 q = *(const int4*)(cnt + base);
        v[0] = q.x; v[1] = q.y; v[2] = q.z; v[3] = q.w;
    } else {
        for (int j = 0; j < 4; j++) if (base + j < nk) v[j] = cnt[base + j];
    }
    int ts = v[0] + v[1] + v[2] + v[3];
    sh[t] = ts; __syncthreads();
    for (int o = 1; o < 256; o <<= 1) {
        int add = (t >= o) ? sh[t - o] : 0;
        __syncthreads();
        sh[t] += add;
        __syncthreads();
    }
    int excl = sh[t] - ts + bsum[b];
    int o0 = excl, o1 = o0 + v[0], o2 = o1 + v[1], o3 = o2 + v[2];
    if (base + 3 < nk) {
        *(int4*)(off + base) = make_int4(o0, o1, o2, o3);
        *(int4*)(cur + base) = make_int4(o0, o1, o2, o3);
    } else {
        int oo[4] = {o0, o1, o2, o3};
        for (int j = 0; j < 4; j++)
            if (base + j < nk) { off[base + j] = oo[j]; cur[base + j] = oo[j]; }
    }
}

__global__ void place_kernel(const int* __restrict__ src, const int* __restrict__ dst,
                             const int* __restrict__ et, int* cur, int* esrc, int E) {
    int e = blockIdx.x * blockDim.x + threadIdx.x;
    if (e >= E) return;
    int key = dst[e] * RR + et[e];
    int pos = atomicAdd(&cur[key], 1);
    esrc[pos] = src[e];
}

// ---------------- split fp32 -> bf16 hi/lo pair ----------------
__global__ void split_kernel(const float* __restrict__ in,
                             __nv_bfloat16* __restrict__ oh, __nv_bfloat16* __restrict__ ol,
                             int n) {
    int t = (blockIdx.x * blockDim.x + threadIdx.x) * 4;
    if (t + 3 >= n) {
        for (int j = 0; j < 4 && t + j < n; j++) {
            __nv_bfloat16 h, l;
            split_bf16(in[t + j], h, l);
            oh[t + j] = h; ol[t + j] = l;
        }
        return;
    }
    float4 v = *(const float4*)(in + t);
    __nv_bfloat16 h0, h1, h2, h3, l0, l1, l2, l3;
    split_bf16(v.x, h0, l0); split_bf16(v.y, h1, l1);
    split_bf16(v.z, h2, l2); split_bf16(v.w, h3, l3);
    __nv_bfloat162 H0 = __halves2bfloat162(h0, h1), H1 = __halves2bfloat162(h2, h3);
    __nv_bfloat162 L0 = __halves2bfloat162(l0, l1), L1 = __halves2bfloat162(l2, l3);
    *(uint2*)(oh + t) = make_uint2(*(uint32_t*)&H0, *(uint32_t*)&H1);
    *(uint2*)(ol + t) = make_uint2(*(uint32_t*)&L0, *(uint32_t*)&L1);
}

// ---------------- aggregation: warp per dst node, outputs pre-split bf16 ----------------
// mean-scaled; empty slots zero-filled (so GEMM needs no masking).
__global__ void agg_kernel(const __nv_bfloat16* __restrict__ Fh,
                           const __nv_bfloat16* __restrict__ Fl,
                           const int* __restrict__ esrc,
                           const int* __restrict__ off, const int* __restrict__ cur,
                           __nv_bfloat16* __restrict__ aggh, __nv_bfloat16* __restrict__ aggl,
                           int M) {
    int w = (blockIdx.x * blockDim.x + threadIdx.x) >> 5;
    int lane = threadIdx.x & 31;
    if (w >= M) return;
#pragma unroll
    for (int rel = 0; rel < RR; rel++) {
        int key = w * RR + rel;
        int s0 = off[key], s1 = cur[key];
        size_t ob = (size_t)w * (RR * HD) + rel * HD + lane * 4;
        if (s0 >= s1) {
            *(uint2*)(aggh + ob) = make_uint2(0u, 0u);
            *(uint2*)(aggl + ob) = make_uint2(0u, 0u);
            continue;
        }
        float a0 = 0.f, a1 = 0.f, a2 = 0.f, a3 = 0.f;
        int snext = esrc[s0];
        for (int e = s0; e < s1; e++) {
            int sc = snext;
            if (e + 1 < s1) snext = esrc[e + 1];
            const uint2 uh = *(const uint2*)(Fh + (size_t)sc * HD + lane * 4);
            const uint2 ul = *(const uint2*)(Fl + (size_t)sc * HD + lane * 4);
            float2 h0 = __bfloat1622float2(*(const __nv_bfloat162*)&uh.x);
            float2 h1 = __bfloat1622float2(*(const __nv_bfloat162*)&uh.y);
            float2 l0 = __bfloat1622float2(*(const __nv_bfloat162*)&ul.x);
            float2 l1 = __bfloat1622float2(*(const __nv_bfloat162*)&ul.y);
            a0 += h0.x + l0.x; a1 += h0.y + l0.y;
            a2 += h1.x + l1.x; a3 += h1.y + l1.y;
        }
        float s = 1.0f / (float)(s1 - s0);
        __nv_bfloat16 h0, h1, h2, h3, l0, l1, l2, l3;
        split_bf16(a0 * s, h0, l0); split_bf16(a1 * s, h1, l1);
        split_bf16(a2 * s, h2, l2); split_bf16(a3 * s, h3, l3);
        __nv_bfloat162 H0 = __halves2bfloat162(h0, h1), H1 = __halves2bfloat162(h2, h3);
        __nv_bfloat162 L0 = __halves2bfloat162(l0, l1), L1 = __halves2bfloat162(l2, l3);
        *(uint2*)(aggh + ob) = make_uint2(*(uint32_t*)&H0, *(uint32_t*)&H1);
        *(uint2*)(aggl + ob) = make_uint2(*(uint32_t*)&L0, *(uint32_t*)&L1);
    }
}

// weight prep: B^T[n][k] split to bf16 hi/lo.  k<128 -> root[k][n], else W[(k-128)][n]
__global__ void prep_kernel(const float* __restrict__ root, const float* __restrict__ W,
                            __nv_bfloat16* Bh, __nv_bfloat16* Bl) {
    int t = blockIdx.x * blockDim.x + threadIdx.x;
    if (t >= 128 * KTOT) return;
    int n = t / KTOT, k = t % KTOT;
    float v = (k < HD) ? root[k * HD + n] : W[(size_t)(k - HD) * HD + n];
    __nv_bfloat16 h, l;
    split_bf16(v, h, l);
    Bh[t] = h;
    Bl[t] = l;
}

// ---------------- pure split-bf16 mma.sync GEMM, 128x128, all-cp.async ----------------
// out = relu( [Xsplit | AggSplit] @ [root;W] + bias ), emitted as (hi,lo) bf16 pairs.
__global__ __launch_bounds__(256, 2) void rgcn_mma(
    const __nv_bfloat16* __restrict__ Xh, const __nv_bfloat16* __restrict__ Xl,
    const __nv_bfloat16* __restrict__ Ah, const __nv_bfloat16* __restrict__ Al,
    const __nv_bfloat16* __restrict__ Bh, const __nv_bfloat16* __restrict__ Bl,
    const float* __restrict__ bias,
    __nv_bfloat16* __restrict__ Hh, __nv_bfloat16* __restrict__ Hl, int M) {

    __shared__ __nv_bfloat16 Ah_s[2][128][AST], Al_s[2][128][AST];
    __shared__ __nv_bfloat16 Bh_s[2][128][AST], Bl_s[2][128][AST];

    const int tid = threadIdx.x;
    const int wid = tid >> 5;
    const int lane = tid & 31;
    const int brow = blockIdx.x * 128;

    // warp tile: 4 (m) x 2 (n); each warp 32 rows x 64 cols
    const int warp_m = wid & 3, warp_n = wid >> 2;
    const int mr0 = warp_m * 32, nc0 = warp_n * 64;

    const int alr = lane & 15, alc = (lane >> 4) << 3;
    const uint32_t aA0h = smem_u32(&Ah_s[0][mr0 + alr][alc]);
    const uint32_t aA1h = smem_u32(&Ah_s[0][mr0 + 16 + alr][alc]);
    const uint32_t aA0l = smem_u32(&Al_s[0][mr0 + alr][alc]);
    const uint32_t aA1l = smem_u32(&Al_s[0][mr0 + 16 + alr][alc]);
    const int blr = (lane & 7) + ((lane >> 4) << 3);
    const int blc = ((lane >> 3) & 1) << 3;
    uint32_t aBhx[4], aBlx[4];
#pragma unroll
    for (int j = 0; j < 4; j++) {
        aBhx[j] = smem_u32(&Bh_s[0][nc0 + blr + j * 16][blc]);
        aBlx[j] = smem_u32(&Bl_s[0][nc0 + blr + j * 16][blc]);
    }
    const uint32_t BUFO = 128 * AST * 2;    // bytes per stage

    float acc[2][8][4];
#pragma unroll
    for (int i = 0; i < 2; i++)
#pragma unroll
        for (int j = 0; j < 8; j++)
#pragma unroll
            for (int q = 0; q < 4; q++) acc[i][j][q] = 0.f;

    // staging: thread -> (row 0..127, 16-elem k half)
    const int arow = tid >> 1;
    const int aks  = (tid & 1) << 4;
    int g = brow + arow;
    if (g >= M) g = M - 1;                  // clamp; garbage rows masked at store

    auto cpA = [&](int c, int buf) {
        const __nv_bfloat16 *sh, *sl;
        if (c < 4) {
            sh = Xh + (size_t)g * HD + c * 32 + aks;
            sl = Xl + (size_t)g * HD + c * 32 + aks;
        } else {
            sh = Ah + (size_t)g * (RR * HD) + (c - 4) * 32 + aks;
            sl = Al + (size_t)g * (RR * HD) + (c - 4) * 32 + aks;
        }
        uint32_t dh = smem_u32(&Ah_s[buf][arow][aks]);
        uint32_t dl = smem_u32(&Al_s[buf][arow][aks]);
        cp_async16(dh, sh);
        cp_async16(dh + 16, sh + 8);
        cp_async16(dl, sl);
        cp_async16(dl + 16, sl + 8);
    };
    auto cpB = [&](int c, int buf) {
        const __nv_bfloat16* bh = Bh + (size_t)arow * KTOT + c * 32 + aks;
        const __nv_bfloat16* bl = Bl + (size_t)arow * KTOT + c * 32 + aks;
        uint32_t dh = smem_u32(&Bh_s[buf][arow][aks]);
        uint32_t dl = smem_u32(&Bl_s[buf][arow][aks]);
        cp_async16(dh, bh);
        cp_async16(dh + 16, bh + 8);
        cp_async16(dl, bl);
        cp_async16(dl + 16, bl + 8);
    };

    // ---- prologue ----
    cpA(0, 0);
    cpB(0, 0);
    cp_commit();
    cp_wait0();
    __syncthreads();

    // ---- mainloop: cp.async + ldsm + HMMA only ----
    for (int c = 0; c < NCHUNK; c++) {
        const int buf = c & 1;
        const uint32_t bo = buf ? BUFO : 0;

        if (c + 1 < NCHUNK) {
            cpA(c + 1, buf ^ 1);
            cpB(c + 1, buf ^ 1);
            cp_commit();
        }

#pragma unroll
        for (int k16 = 0; k16 < 2; k16++) {
            const uint32_t kb = bo + k16 * 32;
            uint32_t Afh[2][4], Afl[2][4];
            ldsm_x4(Afh[0], aA0h + kb);
            ldsm_x4(Afh[1], aA1h + kb);
            ldsm_x4(Afl[0], aA0l + kb);
            ldsm_x4(Afl[1], aA1l + kb);
            uint32_t Bf[8][2];
#pragma unroll
            for (int j = 0; j < 4; j++) {
                uint32_t t[4];
                ldsm_x4(t, aBhx[j] + kb);
                Bf[2 * j][0] = t[0]; Bf[2 * j][1] = t[1];
                Bf[2 * j + 1][0] = t[2]; Bf[2 * j + 1][1] = t[3];
            }
#pragma unroll
            for (int mf = 0; mf < 2; mf++)
#pragma unroll
                for (int nf = 0; nf < 8; nf++) mma16816(acc[mf][nf], Afh[mf], Bf[nf]);
#pragma unroll
            for (int mf = 0; mf < 2; mf++)
#pragma unroll
                for (int nf = 0; nf < 8; nf++) mma16816(acc[mf][nf], Afl[mf], Bf[nf]);
#pragma unroll
            for (int j = 0; j < 4; j++) {
                uint32_t t[4];
                ldsm_x4(t, aBlx[j] + kb);
                Bf[2 * j][0] = t[0]; Bf[2 * j][1] = t[1];
                Bf[2 * j + 1][0] = t[2]; Bf[2 * j + 1][1] = t[3];
            }
#pragma unroll
            for (int mf = 0; mf < 2; mf++)
#pragma unroll
                for (int nf = 0; nf < 8; nf++) mma16816(acc[mf][nf], Afh[mf], Bf[nf]);
        }

        if (c + 1 < NCHUNK) cp_wait0();
        __syncthreads();
    }

    // ---- epilogue: bias + relu -> split bf16 pair store ----
    const int er = lane >> 2, ec = (lane & 3) * 2;
    float2 bv[8];
#pragma unroll
    for (int nf = 0; nf < 8; nf++)
        bv[nf] = *(const float2*)(bias + nc0 + nf * 8 + ec);

#pragma unroll
    for (int mf = 0; mf < 2; mf++) {
#pragma unroll
        for (int half = 0; half < 2; half++) {
            int gr = brow + mr0 + mf * 16 + half * 8 + er;
            if (gr < M) {
                size_t base = (size_t)gr * HD + nc0 + ec;
#pragma unroll
                for (int nf = 0; nf < 8; nf++) {
                    float ox = fmaxf(acc[mf][nf][half * 2]     + bv[nf].x, 0.f);
                    float oy = fmaxf(acc[mf][nf][half * 2 + 1] + bv[nf].y, 0.f);
                    __nv_bfloat16 hx, hy, lx, ly;
                    split_bf16(ox, hx, lx);
                    split_bf16(oy, hy, ly);
                    *(__nv_bfloat162*)(Hh + base + nf * 8) = __halves2bfloat162(hx, hy);
                    *(__nv_bfloat162*)(Hl + base + nf * 8) = __halves2bfloat162(lx, ly);
                }
            }
        }
    }
}

// out[n] = dot(hi+lo, Wc) + bc; one warp per node
__global__ void classify_kernel(const __nv_bfloat16* __restrict__ Hh,
                                const __nv_bfloat16* __restrict__ Hl,
                                const float* __restrict__ Wc,
                                const float* __restrict__ bc, float* __restrict__ out, int M) {
    int t = blockIdx.x * blockDim.x + threadIdx.x;
    int n = t >> 5, lane = t & 31;
    if (n >= M) return;
    const uint2 uh = *(const uint2*)(Hh + (size_t)n * HD + lane * 4);
    const uint2 ul = *(const uint2*)(Hl + (size_t)n * HD + lane * 4);
    float2 h0 = __bfloat1622float2(*(const __nv_bfloat162*)&uh.x);
    float2 h1 = __bfloat1622float2(*(const __nv_bfloat162*)&uh.y);
    float2 l0 = __bfloat1622float2(*(const __nv_bfloat162*)&ul.x);
    float2 l1 = __bfloat1622float2(*(const __nv_bfloat162*)&ul.y);
    float4 w = *(const float4*)(Wc + lane * 4);
    float s = (h0.x + l0.x) * w.x + (h0.y + l0.y) * w.y
            + (h1.x + l1.x) * w.z + (h1.y + l1.y) * w.w;
#pragma unroll
    for (int o = 16; o; o >>= 1) s += __shfl_xor_sync(0xffffffffu, s, o);
    if (lane == 0) out[n] = s + bc[0];
}

// ---------------- launch ----------------
extern "C" void kernel_launch(void* const* d_in, const int* in_sizes, int n_in,
                              void* d_out, int out_size) {
    const float* x  = (const float*)d_in[0];
    const int*   ei = (const int*)d_in[1];
    const int*   et = (const int*)d_in[2];
    const float* W1 = (const float*)d_in[3];
    const float* r1 = (const float*)d_in[4];
    const float* b1 = (const float*)d_in[5];
    const float* W2 = (const float*)d_in[6];
    const float* r2 = (const float*)d_in[7];
    const float* b2 = (const float*)d_in[8];
    const float* Wc = (const float*)d_in[9];
    const float* bc = (const float*)d_in[10];

    int M = in_sizes[0] / HD;    // 50000
    int E = in_sizes[1] / 2;     // 500000
    const int* src = ei;
    const int* dst = ei + E;

    __nv_bfloat16 *aggh, *aggl, *xh, *xl, *h1h, *h1l, *h2h, *h2l;
    int *cnt, *off, *cur, *bsum, *esrc;
    __nv_bfloat16 *Bh1, *Bl1, *Bh2, *Bl2;
    cudaGetSymbolAddress((void**)&aggh, g_aggh);
    cudaGetSymbolAddress((void**)&aggl, g_aggl);
    cudaGetSymbolAddress((void**)&cnt, g_cnt);
    cudaGetSymbolAddress((void**)&off, g_off);
    cudaGetSymbolAddress((void**)&cur, g_cur);
    cudaGetSymbolAddress((void**)&bsum, g_bsum);
    cudaGetSymbolAddress((void**)&esrc, g_esrc);
    cudaGetSymbolAddress((void**)&xh, g_xh);
    cudaGetSymbolAddress((void**)&xl, g_xl);
    cudaGetSymbolAddress((void**)&h1h, g_h1h);
    cudaGetSymbolAddress((void**)&h1l, g_h1l);
    cudaGetSymbolAddress((void**)&h2h, g_h2h);
    cudaGetSymbolAddress((void**)&h2l, g_h2l);
    cudaGetSymbolAddress((void**)&Bh1, g_Bh1);
    cudaGetSymbolAddress((void**)&Bl1, g_Bl1);
    cudaGetSymbolAddress((void**)&Bh2, g_Bh2);
    cudaGetSymbolAddress((void**)&Bl2, g_Bl2);

    int nk = M * RR;
    int nb = (nk + 1023) / 1024;
    int mblocks = (M + 127) / 128;                // 391
    int eblocks = (E + 255) / 256;
    int pblocks = (128 * KTOT + 255) / 256;
    int ablocks = (M * 32 + 255) / 256;
    int xblocks = (M * HD / 4 + 255) / 256;

    // weight + feature prep (static per call)
    prep_kernel<<<pblocks, 256>>>(r1, W1, Bh1, Bl1);
    prep_kernel<<<pblocks, 256>>>(r2, W2, Bh2, Bl2);
    split_kernel<<<xblocks, 256>>>(x, xh, xl, M * HD);

    // ---- CSR build (shared by both layers) ----
    cudaMemsetAsync(cnt, 0, nk * sizeof(int));
    count_kernel<<<eblocks, 256>>>(dst, et, cnt, E);
    scan1_kernel<<<nb, 256>>>(cnt, bsum, nk);
    scan2_kernel<<<1, 512>>>(bsum, nb);
    scan3_kernel<<<nb, 256>>>(cnt, bsum, off, cur, nk);
    place_kernel<<<eblocks, 256>>>(src, dst, et, cur, esrc, E);

    // ---- layer 1 ----
    agg_kernel<<<ablocks, 256>>>(xh, xl, esrc, off, cur, aggh, aggl, M);
    rgcn_mma<<<mblocks, 256>>>(xh, xl, aggh, aggl, Bh1, Bl1, b1, h1h, h1l, M);

    // ---- layer 2 ----
    agg_kernel<<<ablocks, 256>>>(h1h, h1l, esrc, off, cur, aggh, aggl, M);
    rgcn_mma<<<mblocks, 256>>>(h1h, h1l, aggh, aggl, Bh2, Bl2, b2, h2h, h2l, M);

    // ---- classifier ----
    classify_kernel<<<((M * 32) + 255) / 256, 256>>>(h2h, h2l, Wc, bc, (float*)d_out, M);
}

// round 9
// speedup vs baseline: 1.2321x; 1.2321x over previous
#include <cuda_runtime.h>
#include <cuda_fp16.h>
#include <cstdint>

#define HD   128
#define RR   8
#define NMAX 50000
#define EMAX 500000
#define NK   (NMAX * RR)        // 400000 bins
#define KTOT (HD + RR * HD)     // 1152
#define NCHUNK 36               // 1152 / 32
#define AST  40                 // smem row stride (fp16 elems): 32 + 8 pad

// ---------------- scratch (static device globals; no allocation) ----------------
__device__ float g_agg[(size_t)NMAX * RR * HD];     // [N, 8, 128]
__device__ int   g_cnt[NK];
__device__ int   g_off[NK];
__device__ int   g_cur[NK];
__device__ int   g_bsum[512];
__device__ int   g_esrc[EMAX];
__device__ float g_h1[(size_t)NMAX * HD];
__device__ float g_h2[(size_t)NMAX * HD];
__device__ __half g_Bh1[128 * KTOT];                // B^T hi/lo fp16: [n][k]
__device__ __half g_Bl1[128 * KTOT];
__device__ __half g_Bh2[128 * KTOT];
__device__ __half g_Bl2[128 * KTOT];

// ---------------- mma.sync / ldmatrix / cp.async helpers (base PTX, sm_80+) -----
__device__ __forceinline__ uint32_t smem_u32(const void* p) {
    return (uint32_t)__cvta_generic_to_shared(p);
}
__device__ __forceinline__ void ldsm_x4(uint32_t* r, uint32_t addr) {
    asm volatile("ldmatrix.sync.aligned.m8n8.x4.shared.b16 {%0,%1,%2,%3}, [%4];"
                 : "=r"(r[0]), "=r"(r[1]), "=r"(r[2]), "=r"(r[3]) : "r"(addr));
}
__device__ __forceinline__ void mma16816(float* d, const uint32_t* a, const uint32_t* b) {
    asm volatile(
        "mma.sync.aligned.m16n8k16.row.col.f32.f16.f16.f32 "
        "{%0,%1,%2,%3}, {%4,%5,%6,%7}, {%8,%9}, {%0,%1,%2,%3};"
        : "+f"(d[0]), "+f"(d[1]), "+f"(d[2]), "+f"(d[3])
        : "r"(a[0]), "r"(a[1]), "r"(a[2]), "r"(a[3]), "r"(b[0]), "r"(b[1]));
}
__device__ __forceinline__ void cp_async16(uint32_t smem_dst, const void* gptr) {
    asm volatile("cp.async.cg.shared.global [%0], [%1], 16;"
                 :: "r"(smem_dst), "l"(gptr));
}
__device__ __forceinline__ void cp_commit() { asm volatile("cp.async.commit_group;"); }
__device__ __forceinline__ void cp_wait0()  { asm volatile("cp.async.wait_group 0;"); }

// ---------------- CSR build: count -> scan -> place ----------------
__global__ void count_kernel(const int* __restrict__ dst, const int* __restrict__ et,
                             int* cnt, int E) {
    int e = blockIdx.x * blockDim.x + threadIdx.x;
    if (e < E) atomicAdd(&cnt[dst[e] * RR + et[e]], 1);
}

__global__ void scan1_kernel(const int* __restrict__ cnt, int* bsum, int nk) {
    __shared__ int sh[256];
    int b = blockIdx.x, t = threadIdx.x;
    int base = b * 1024 + t * 4;
    int s = 0;
    if (base + 3 < nk) {
        int4 v = *(const int4*)(cnt + base);
        s = v.x + v.y + v.z + v.w;
    } else {
        for (int j = 0; j < 4; j++) if (base + j < nk) s += cnt[base + j];
    }
    sh[t] = s; __syncthreads();
    for (int o = 128; o; o >>= 1) { if (t < o) sh[t] += sh[t + o]; __syncthreads(); }
    if (t == 0) bsum[b] = sh[0];
}

__global__ void scan2_kernel(int* bsum, int nb) {
    __shared__ int sh[512];
    int t = threadIdx.x;
    int v = (t < nb) ? bsum[t] : 0;
    sh[t] = v; __syncthreads();
    for (int o = 1; o < 512; o <<= 1) {
        int add = (t >= o) ? sh[t - o] : 0;
        __syncthreads();
        sh[t] += add;
        __syncthreads();
    }
    if (t < nb) bsum[t] = sh[t] - v;   // exclusive
}

__global__ void scan3_kernel(const int* __restrict__ cnt, const int* __restrict__ bsum,
                             int* off, int* cur, int nk) {
    __shared__ int sh[256];
    int b = blockIdx.x, t = threadIdx.x;
    int base = b * 1024 + t * 4;
    int v[4] = {0, 0, 0, 0};
    if (base + 3 < nk) {
        int4 q = *(const int4*)(cnt + base);
        v[0] = q.x; v[1] = q.y; v[2] = q.z; v[3] = q.w;
    } else {
        for (int j = 0; j < 4; j++) if (base + j < nk) v[j] = cnt[base + j];
    }
    int ts = v[0] + v[1] + v[2] + v[3];
    sh[t] = ts; __syncthreads();
    for (int o = 1; o < 256; o <<= 1) {
        int add = (t >= o) ? sh[t - o] : 0;
        __syncthreads();
        sh[t] += add;
        __syncthreads();
    }
    int excl = sh[t] - ts + bsum[b];
    int o0 = excl, o1 = o0 + v[0], o2 = o1 + v[1], o3 = o2 + v[2];
    if (base + 3 < nk) {
        *(int4*)(off + base) = make_int4(o0, o1, o2, o3);
        *(int4*)(cur + base) = make_int4(o0, o1, o2, o3);
    } else {
        int oo[4] = {o0, o1, o2, o3};
        for (int j = 0; j < 4; j++)
            if (base + j < nk) { off[base + j] = oo[j]; cur[base + j] = oo[j]; }
    }
}

__global__ void place_kernel(const int* __restrict__ src, const int* __restrict__ dst,
                             const int* __restrict__ et, int* cur, int* esrc, int E) {
    int e = blockIdx.x * blockDim.x + threadIdx.x;
    if (e >= E) return;
    int key = dst[e] * RR + et[e];
    int pos = atomicAdd(&cur[key], 1);
    esrc[pos] = src[e];
}

// ---------------- atomic-free aggregation: warp per dst node ----------------
__global__ void agg_kernel(const float* __restrict__ feat, const int* __restrict__ esrc,
                           const int* __restrict__ off, const int* __restrict__ cur,
                           float* __restrict__ agg, int M) {
    int w = (blockIdx.x * blockDim.x + threadIdx.x) >> 5;
    int lane = threadIdx.x & 31;
    if (w >= M) return;
#pragma unroll
    for (int rel = 0; rel < RR; rel++) {
        int key = w * RR + rel;
        int s0 = off[key], s1 = cur[key];
        if (s0 >= s1) continue;
        float4 acc = make_float4(0.f, 0.f, 0.f, 0.f);
        int snext = esrc[s0];
        for (int e = s0; e < s1; e++) {
            int sc = snext;
            if (e + 1 < s1) snext = esrc[e + 1];
            float4 v = *(const float4*)(feat + (size_t)sc * HD + lane * 4);
            acc.x += v.x; acc.y += v.y; acc.z += v.z; acc.w += v.w;
        }
        *(float4*)(agg + (size_t)w * (RR * HD) + rel * HD + lane * 4) = acc;
    }
}

// weight prep: B^T[n][k] split to fp16 hi/lo.  k<128 -> root[k][n], else W[(k-128)][n]
__global__ void prep_kernel(const float* __restrict__ root, const float* __restrict__ W,
                            __half* Bh, __half* Bl) {
    int t = blockIdx.x * blockDim.x + threadIdx.x;
    if (t >= 128 * KTOT) return;
    int n = t / KTOT, k = t % KTOT;
    float v = (k < HD) ? root[k * HD + n] : W[(size_t)(k - HD) * HD + n];
    __half h = __float2half(v);
    Bh[t] = h;
    Bl[t] = __float2half(v - __half2float(h));
}

// ---------------- fp16 2-term mma.sync GEMM, 128x128, double-buffered ----------------
// out = relu( [X | invcnt*agg]_fp16 @ (Bh + Bl) + bias );  B exact in fp16 pair,
// A single-rounded fp16.  InvS==0 masks empty (row,rel) slots.
__global__ __launch_bounds__(256, 2) void rgcn_mma(
    const float* __restrict__ X, const float* __restrict__ agg,
    const int* __restrict__ cnt,
    const __half* __restrict__ Bh, const __half* __restrict__ Bl,
    const float* __restrict__ bias, float* __restrict__ out, int M) {

    __shared__ __half A_s[2][128][AST];
    __shared__ __half Bh_s[2][128][AST], Bl_s[2][128][AST];
    __shared__ float InvS[128 * RR];

    const int tid = threadIdx.x;
    const int wid = tid >> 5;
    const int lane = tid & 31;
    const int brow = blockIdx.x * 128;

    for (int i = tid; i < 128 * RR; i += 256) {
        int r = i >> 3, rel = i & 7;
        int gg = brow + r;
        int c = (gg < M) ? cnt[gg * RR + rel] : 0;
        InvS[r * RR + rel] = (c > 0) ? 1.0f / (float)c : 0.0f;
    }

    // warp tile: 4 (m) x 2 (n); each warp 32 rows x 64 cols
    const int warp_m = wid & 3, warp_n = wid >> 2;
    const int mr0 = warp_m * 32, nc0 = warp_n * 64;

    const int alr = lane & 15, alc = (lane >> 4) << 3;
    const uint32_t aA0 = smem_u32(&A_s[0][mr0 + alr][alc]);
    const uint32_t aA1 = smem_u32(&A_s[0][mr0 + 16 + alr][alc]);
    const int blr = (lane & 7) + ((lane >> 4) << 3);
    const int blc = ((lane >> 3) & 1) << 3;
    uint32_t aBhx[4], aBlx[4];
#pragma unroll
    for (int j = 0; j < 4; j++) {
        aBhx[j] = smem_u32(&Bh_s[0][nc0 + blr + j * 16][blc]);
        aBlx[j] = smem_u32(&Bl_s[0][nc0 + blr + j * 16][blc]);
    }
    const uint32_t BUFO = 128 * AST * 2;    // bytes per stage

    float acc[2][8][4];
#pragma unroll
    for (int i = 0; i < 2; i++)
#pragma unroll
        for (int j = 0; j < 8; j++)
#pragma unroll
            for (int q = 0; q < 4; q++) acc[i][j][q] = 0.f;

    const int arow = tid >> 1;            // 0..127
    const int aks  = (tid & 1) << 4;      // k offset 0 / 16
    const int g    = brow + arow;

    auto loadA = [&](int c, float4* v, float& s) {
        const float* ap;
        if (c < 4) { ap = X + (size_t)g * HD + c * 32 + aks; s = 1.0f; }
        else {
            ap = agg + (size_t)g * (RR * HD) + (c - 4) * 32 + aks;
            s = InvS[arow * RR + ((c - 4) >> 2)];
        }
#pragma unroll
        for (int i = 0; i < 4; i++)
            v[i] = (g < M) ? *(const float4*)(ap + i * 4) : make_float4(0.f, 0.f, 0.f, 0.f);
    };
    auto cpB = [&](int c, int buf) {
        const char* bh = (const char*)(Bh + (size_t)arow * KTOT + c * 32 + aks);
        const char* bl = (const char*)(Bl + (size_t)arow * KTOT + c * 32 + aks);
        uint32_t dh = smem_u32(&Bh_s[buf][arow][aks]);
        uint32_t dl = smem_u32(&Bl_s[buf][arow][aks]);
        cp_async16(dh, bh);
        cp_async16(dh + 16, bh + 16);
        cp_async16(dl, bl);
        cp_async16(dl + 16, bl + 16);
    };
    auto storeA = [&](const float4* v, float s, int buf) {
        __half2* a2 = (__half2*)&A_s[buf][arow][aks];
#pragma unroll
        for (int i = 0; i < 4; i++) {
            a2[i * 2]     = __floats2half2_rn(v[i].x * s, v[i].y * s);
            a2[i * 2 + 1] = __floats2half2_rn(v[i].z * s, v[i].w * s);
        }
    };

    // ---- prologue ----
    {
        float4 pv[4]; float ps;
        loadA(0, pv, ps);
        cpB(0, 0);
        cp_commit();
        storeA(pv, ps, 0);
        cp_wait0();
    }
    __syncthreads();

    // ---- mainloop ----
    for (int c = 0; c < NCHUNK; c++) {
        const int buf = c & 1;
        const uint32_t bo = buf ? BUFO : 0;

        float4 pv[4]; float ps;
        if (c + 1 < NCHUNK) {
            loadA(c + 1, pv, ps);
            cpB(c + 1, buf ^ 1);
            cp_commit();
        }

#pragma unroll
        for (int k16 = 0; k16 < 2; k16++) {
            const uint32_t kb = bo + k16 * 32;
            uint32_t Af[2][4];
            ldsm_x4(Af[0], aA0 + kb);
            ldsm_x4(Af[1], aA1 + kb);
            uint32_t Bf[8][2];
#pragma unroll
            for (int j = 0; j < 4; j++) {
                uint32_t t[4];
                ldsm_x4(t, aBhx[j] + kb);
                Bf[2 * j][0] = t[0]; Bf[2 * j][1] = t[1];
                Bf[2 * j + 1][0] = t[2]; Bf[2 * j + 1][1] = t[3];
            }
#pragma unroll
            for (int mf = 0; mf < 2; mf++)
#pragma unroll
                for (int nf = 0; nf < 8; nf++) mma16816(acc[mf][nf], Af[mf], Bf[nf]);
#pragma unroll
            for (int j = 0; j < 4; j++) {
                uint32_t t[4];
                ldsm_x4(t, aBlx[j] + kb);
                Bf[2 * j][0] = t[0]; Bf[2 * j][1] = t[1];
                Bf[2 * j + 1][0] = t[2]; Bf[2 * j + 1][1] = t[3];
            }
#pragma unroll
            for (int mf = 0; mf < 2; mf++)
#pragma unroll
                for (int nf = 0; nf < 8; nf++) mma16816(acc[mf][nf], Af[mf], Bf[nf]);
        }

        if (c + 1 < NCHUNK) {
            storeA(pv, ps, buf ^ 1);
            cp_wait0();
        }
        __syncthreads();
    }

    // ---- epilogue: bias + relu + store ----
    const int er = lane >> 2, ec = (lane & 3) * 2;
    float2 bv[8];
#pragma unroll
    for (int nf = 0; nf < 8; nf++)
        bv[nf] = *(const float2*)(bias + nc0 + nf * 8 + ec);

#pragma unroll
    for (int mf = 0; mf < 2; mf++) {
#pragma unroll
        for (int half = 0; half < 2; half++) {
            int gr = brow + mr0 + mf * 16 + half * 8 + er;
            if (gr < M) {
                float* op = out + (size_t)gr * HD + nc0 + ec;
#pragma unroll
                for (int nf = 0; nf < 8; nf++) {
                    float2 o;
                    o.x = fmaxf(acc[mf][nf][half * 2]     + bv[nf].x, 0.f);
                    o.y = fmaxf(acc[mf][nf][half * 2 + 1] + bv[nf].y, 0.f);
                    *(float2*)(op + nf * 8) = o;
                }
            }
        }
    }
}

// out[n] = dot(h2[n,:], Wc) + bc; one warp per node
__global__ void classify_kernel(const float* __restrict__ h, const float* __restrict__ Wc,
                                const float* __restrict__ bc, float* __restrict__ out, int M) {
    int t = blockIdx.x * blockDim.x + threadIdx.x;
    int n = t >> 5, lane = t & 31;
    if (n >= M) return;
    float4 v = *(const float4*)(h + (size_t)n * HD + lane * 4);
    float4 w = *(const float4*)(Wc + lane * 4);
    float s = v.x * w.x + v.y * w.y + v.z * w.z + v.w * w.w;
#pragma unroll
    for (int o = 16; o; o >>= 1) s += __shfl_xor_sync(0xffffffffu, s, o);
    if (lane == 0) out[n] = s + bc[0];
}

// ---------------- launch ----------------
extern "C" void kernel_launch(void* const* d_in, const int* in_sizes, int n_in,
                              void* d_out, int out_size) {
    const float* x  = (const float*)d_in[0];
    const int*   ei = (const int*)d_in[1];
    const int*   et = (const int*)d_in[2];
    const float* W1 = (const float*)d_in[3];
    const float* r1 = (const float*)d_in[4];
    const float* b1 = (const float*)d_in[5];
    const float* W2 = (const float*)d_in[6];
    const float* r2 = (const float*)d_in[7];
    const float* b2 = (const float*)d_in[8];
    const float* Wc = (const float*)d_in[9];
    const float* bc = (const float*)d_in[10];

    int M = in_sizes[0] / HD;    // 50000
    int E = in_sizes[1] / 2;     // 500000
    const int* src = ei;
    const int* dst = ei + E;

    float *agg, *h1, *h2;
    int *cnt, *off, *cur, *bsum, *esrc;
    __half *Bh1, *Bl1, *Bh2, *Bl2;
    cudaGetSymbolAddress((void**)&agg, g_agg);
    cudaGetSymbolAddress((void**)&cnt, g_cnt);
    cudaGetSymbolAddress((void**)&off, g_off);
    cudaGetSymbolAddress((void**)&cur, g_cur);
    cudaGetSymbolAddress((void**)&bsum, g_bsum);
    cudaGetSymbolAddress((void**)&esrc, g_esrc);
    cudaGetSymbolAddress((void**)&h1, g_h1);
    cudaGetSymbolAddress((void**)&h2, g_h2);
    cudaGetSymbolAddress((void**)&Bh1, g_Bh1);
    cudaGetSymbolAddress((void**)&Bl1, g_Bl1);
    cudaGetSymbolAddress((void**)&Bh2, g_Bh2);
    cudaGetSymbolAddress((void**)&Bl2, g_Bl2);

    int nk = M * RR;
    int nb = (nk + 1023) / 1024;
    int mblocks = (M + 127) / 128;                // 391
    int eblocks = (E + 255) / 256;
    int pblocks = (128 * KTOT + 255) / 256;
    int ablocks = (M * 32 + 255) / 256;

    // weight prep (static per call)
    prep_kernel<<<pblocks, 256>>>(r1, W1, Bh1, Bl1);
    prep_kernel<<<pblocks, 256>>>(r2, W2, Bh2, Bl2);

    // ---- CSR build (shared by both layers) ----
    cudaMemsetAsync(cnt, 0, nk * sizeof(int));
    count_kernel<<<eblocks, 256>>>(dst, et, cnt, E);
    scan1_kernel<<<nb, 256>>>(cnt, bsum, nk);
    scan2_kernel<<<1, 512>>>(bsum, nb);
    scan3_kernel<<<nb, 256>>>(cnt, bsum, off, cur, nk);
    place_kernel<<<eblocks, 256>>>(src, dst, et, cur, esrc, E);

    // ---- layer 1 ----
    agg_kernel<<<ablocks, 256>>>(x, esrc, off, cur, agg, M);
    rgcn_mma<<<mblocks, 256>>>(x, agg, cnt, Bh1, Bl1, b1, h1, M);

    // ---- layer 2 ----
    agg_kernel<<<ablocks, 256>>>(h1, esrc, off, cur, agg, M);
    rgcn_mma<<<mblocks, 256>>>(h1, agg, cnt, Bh2, Bl2, b2, h2, M);

    // ---- classifier ----
    classify_kernel<<<((M * 32) + 255) / 256, 256>>>(h2, Wc, bc, (float*)d_out, M);
}

// round 10
// speedup vs baseline: 1.4439x; 1.1719x over previous
#include <cuda_runtime.h>
#include <cuda_fp16.h>
#include <cstdint>

#define HD   128
#define RR   8
#define NMAX 50000
#define EMAX 500000
#define NK   (NMAX * RR)        // 400000 bins
#define KTOT (HD + RR * HD)     // 1152
#define NCHUNK 36               // 1152 / 32
#define AST  40                 // smem row stride (fp16 elems): 32 + 8 pad

// ---------------- scratch (static device globals; no allocation) ----------------
__device__ __half g_aggh[(size_t)NMAX * RR * HD];   // [N,8,128] fp16, mean applied
__device__ int   g_cnt[NK];
__device__ int   g_off[NK];
__device__ int   g_cur[NK];
__device__ int   g_bsum[512];
__device__ int   g_esrc[EMAX];
__device__ __half g_xh[(size_t)NMAX * HD];
__device__ __half g_h1[(size_t)NMAX * HD];
__device__ __half g_h2[(size_t)NMAX * HD];
__device__ __half g_Bh1[128 * KTOT];                // B^T hi/lo fp16: [n][k]
__device__ __half g_Bl1[128 * KTOT];
__device__ __half g_Bh2[128 * KTOT];
__device__ __half g_Bl2[128 * KTOT];

// ---------------- mma.sync / ldmatrix / cp.async helpers (base PTX, sm_80+) -----
__device__ __forceinline__ uint32_t smem_u32(const void* p) {
    return (uint32_t)__cvta_generic_to_shared(p);
}
__device__ __forceinline__ void ldsm_x4(uint32_t* r, uint32_t addr) {
    asm volatile("ldmatrix.sync.aligned.m8n8.x4.shared.b16 {%0,%1,%2,%3}, [%4];"
                 : "=r"(r[0]), "=r"(r[1]), "=r"(r[2]), "=r"(r[3]) : "r"(addr));
}
__device__ __forceinline__ void mma16816(float* d, const uint32_t* a, const uint32_t* b) {
    asm volatile(
        "mma.sync.aligned.m16n8k16.row.col.f32.f16.f16.f32 "
        "{%0,%1,%2,%3}, {%4,%5,%6,%7}, {%8,%9}, {%0,%1,%2,%3};"
        : "+f"(d[0]), "+f"(d[1]), "+f"(d[2]), "+f"(d[3])
        : "r"(a[0]), "r"(a[1]), "r"(a[2]), "r"(a[3]), "r"(b[0]), "r"(b[1]));
}
__device__ __forceinline__ void cp_async16(uint32_t smem_dst, const void* gptr) {
    asm volatile("cp.async.cg.shared.global [%0], [%1], 16;"
                 :: "r"(smem_dst), "l"(gptr));
}
__device__ __forceinline__ void cp_commit() { asm volatile("cp.async.commit_group;"); }
__device__ __forceinline__ void cp_wait0()  { asm volatile("cp.async.wait_group 0;"); }

// ---------------- CSR build: count -> scan -> place ----------------
__global__ void count_kernel(const int* __restrict__ dst, const int* __restrict__ et,
                             int* cnt, int E) {
    int e = blockIdx.x * blockDim.x + threadIdx.x;
    if (e < E) atomicAdd(&cnt[dst[e] * RR + et[e]], 1);
}

__global__ void scan1_kernel(const int* __restrict__ cnt, int* bsum, int nk) {
    __shared__ int sh[256];
    int b = blockIdx.x, t = threadIdx.x;
    int base = b * 1024 + t * 4;
    int s = 0;
    if (base + 3 < nk) {
        int4 v = *(const int4*)(cnt + base);
        s = v.x + v.y + v.z + v.w;
    } else {
        for (int j = 0; j < 4; j++) if (base + j < nk) s += cnt[base + j];
    }
    sh[t] = s; __syncthreads();
    for (int o = 128; o; o >>= 1) { if (t < o) sh[t] += sh[t + o]; __syncthreads(); }
    if (t == 0) bsum[b] = sh[0];
}

__global__ void scan2_kernel(int* bsum, int nb) {
    __shared__ int sh[512];
    int t = threadIdx.x;
    int v = (t < nb) ? bsum[t] : 0;
    sh[t] = v; __syncthreads();
    for (int o = 1; o < 512; o <<= 1) {
        int add = (t >= o) ? sh[t - o] : 0;
        __syncthreads();
        sh[t] += add;
        __syncthreads();
    }
    if (t < nb) bsum[t] = sh[t] - v;   // exclusive
}

__global__ void scan3_kernel(const int* __restrict__ cnt, const int* __restrict__ bsum,
                             int* off, int* cur, int nk) {
    __shared__ int sh[256];
    int b = blockIdx.x, t = threadIdx.x;
    int base = b * 1024 + t * 4;
    int v[4] = {0, 0, 0, 0};
    if (base + 3 < nk) {
        int4 q = *(const int4*)(cnt + base);
        v[0] = q.x; v[1] = q.y; v[2] = q.z; v[3] = q.w;
    } else {
        for (int j = 0; j < 4; j++) if (base + j < nk) v[j] = cnt[base + j];
    }
    int ts = v[0] + v[1] + v[2] + v[3];
    sh[t] = ts; __syncthreads();
    for (int o = 1; o < 256; o <<= 1) {
        int add = (t >= o) ? sh[t - o] : 0;
        __syncthreads();
        sh[t] += add;
        __syncthreads();
    }
    int excl = sh[t] - ts + bsum[b];
    int o0 = excl, o1 = o0 + v[0], o2 = o1 + v[1], o3 = o2 + v[2];
    if (base + 3 < nk) {
        *(int4*)(off + base) = make_int4(o0, o1, o2, o3);
        *(int4*)(cur + base) = make_int4(o0, o1, o2, o3);
    } else {
        int oo[4] = {o0, o1, o2, o3};
        for (int j = 0; j < 4; j++)
            if (base + j < nk) { off[base + j] = oo[j]; cur[base + j] = oo[j]; }
    }
}

__global__ void place_kernel(const int* __restrict__ src, const int* __restrict__ dst,
                             const int* __restrict__ et, int* cur, int* esrc, int E) {
    int e = blockIdx.x * blockDim.x + threadIdx.x;
    if (e >= E) return;
    int key = dst[e] * RR + et[e];
    int pos = atomicAdd(&cur[key], 1);
    esrc[pos] = src[e];
}

// ---------------- fp32 -> fp16 convert ----------------
__global__ void tohalf_kernel(const float* __restrict__ in, __half* __restrict__ out, int n) {
    int t = (blockIdx.x * blockDim.x + threadIdx.x) * 4;
    if (t + 3 >= n) {
        for (int j = 0; j < 4 && t + j < n; j++) out[t + j] = __float2half(in[t + j]);
        return;
    }
    float4 v = *(const float4*)(in + t);
    __half2 a = __floats2half2_rn(v.x, v.y), b = __floats2half2_rn(v.z, v.w);
    *(uint2*)(out + t) = make_uint2(*(uint32_t*)&a, *(uint32_t*)&b);
}

// ---------------- aggregation: warp per dst node, fp16 in/out, mean applied ------
__global__ void agg_kernel(const __half* __restrict__ feat, const int* __restrict__ esrc,
                           const int* __restrict__ off, const int* __restrict__ cur,
                           __half* __restrict__ agg, int M) {
    int w = (blockIdx.x * blockDim.x + threadIdx.x) >> 5;
    int lane = threadIdx.x & 31;
    if (w >= M) return;
#pragma unroll
    for (int rel = 0; rel < RR; rel++) {
        int key = w * RR + rel;
        int s0 = off[key], s1 = cur[key];
        size_t ob = (size_t)w * (RR * HD) + rel * HD + lane * 4;
        if (s0 >= s1) {
            *(uint2*)(agg + ob) = make_uint2(0u, 0u);
            continue;
        }
        float a0 = 0.f, a1 = 0.f, a2 = 0.f, a3 = 0.f;
        int snext = esrc[s0];
        for (int e = s0; e < s1; e++) {
            int sc = snext;
            if (e + 1 < s1) snext = esrc[e + 1];
            uint2 u = *(const uint2*)(feat + (size_t)sc * HD + lane * 4);
            float2 f0 = __half22float2(*(const __half2*)&u.x);
            float2 f1 = __half22float2(*(const __half2*)&u.y);
            a0 += f0.x; a1 += f0.y; a2 += f1.x; a3 += f1.y;
        }
        float s = 1.0f / (float)(s1 - s0);
        __half2 h0 = __floats2half2_rn(a0 * s, a1 * s);
        __half2 h1 = __floats2half2_rn(a2 * s, a3 * s);
        *(uint2*)(agg + ob) = make_uint2(*(uint32_t*)&h0, *(uint32_t*)&h1);
    }
}

// weight prep: B^T[n][k] split to fp16 hi/lo.  k<128 -> root[k][n], else W[(k-128)][n]
__global__ void prep_kernel(const float* __restrict__ root, const float* __restrict__ W,
                            __half* Bh, __half* Bl) {
    int t = blockIdx.x * blockDim.x + threadIdx.x;
    if (t >= 128 * KTOT) return;
    int n = t / KTOT, k = t % KTOT;
    float v = (k < HD) ? root[k * HD + n] : W[(size_t)(k - HD) * HD + n];
    __half h = __float2half(v);
    Bh[t] = h;
    Bl[t] = __float2half(v - __half2float(h));
}

// ---------------- fp16 2-term mma.sync GEMM, all cp.async ----------------
// out_fp16 = relu( [Xh | Aggh] @ (Bh + Bl) + bias )
__global__ __launch_bounds__(256, 2) void rgcn_mma(
    const __half* __restrict__ Xh, const __half* __restrict__ Aggh,
    const __half* __restrict__ Bh, const __half* __restrict__ Bl,
    const float* __restrict__ bias, __half* __restrict__ Hout, int M) {

    __shared__ __half A_s[2][128][AST];
    __shared__ __half Bh_s[2][128][AST], Bl_s[2][128][AST];

    const int tid = threadIdx.x;
    const int wid = tid >> 5;
    const int lane = tid & 31;
    const int brow = blockIdx.x * 128;

    // warp tile: 4 (m) x 2 (n); each warp 32 rows x 64 cols
    const int warp_m = wid & 3, warp_n = wid >> 2;
    const int mr0 = warp_m * 32, nc0 = warp_n * 64;

    const int alr = lane & 15, alc = (lane >> 4) << 3;
    const uint32_t aA0 = smem_u32(&A_s[0][mr0 + alr][alc]);
    const uint32_t aA1 = smem_u32(&A_s[0][mr0 + 16 + alr][alc]);
    const int blr = (lane & 7) + ((lane >> 4) << 3);
    const int blc = ((lane >> 3) & 1) << 3;
    uint32_t aBhx[4], aBlx[4];
#pragma unroll
    for (int j = 0; j < 4; j++) {
        aBhx[j] = smem_u32(&Bh_s[0][nc0 + blr + j * 16][blc]);
        aBlx[j] = smem_u32(&Bl_s[0][nc0 + blr + j * 16][blc]);
    }
    const uint32_t BUFO = 128 * AST * 2;    // bytes per stage

    float acc[2][8][4];
#pragma unroll
    for (int i = 0; i < 2; i++)
#pragma unroll
        for (int j = 0; j < 8; j++)
#pragma unroll
            for (int q = 0; q < 4; q++) acc[i][j][q] = 0.f;

    // staging: thread -> (row 0..127, 16-elem k half)
    const int arow = tid >> 1;
    const int aks  = (tid & 1) << 4;
    int g = brow + arow;
    if (g >= M) g = M - 1;                  // clamp; garbage rows masked at store

    auto cpA = [&](int c, int buf) {
        const __half* s = (c < 4)
            ? Xh + (size_t)g * HD + c * 32 + aks
            : Aggh + (size_t)g * (RR * HD) + (c - 4) * 32 + aks;
        uint32_t d = smem_u32(&A_s[buf][arow][aks]);
        cp_async16(d, s);
        cp_async16(d + 16, s + 8);
    };
    auto cpB = [&](int c, int buf) {
        const __half* bh = Bh + (size_t)arow * KTOT + c * 32 + aks;
        const __half* bl = Bl + (size_t)arow * KTOT + c * 32 + aks;
        uint32_t dh = smem_u32(&Bh_s[buf][arow][aks]);
        uint32_t dl = smem_u32(&Bl_s[buf][arow][aks]);
        cp_async16(dh, bh);
        cp_async16(dh + 16, bh + 8);
        cp_async16(dl, bl);
        cp_async16(dl + 16, bl + 8);
    };

    // ---- prologue ----
    cpA(0, 0);
    cpB(0, 0);
    cp_commit();
    cp_wait0();
    __syncthreads();

    // ---- mainloop: cp.async + ldsm + HMMA only ----
    for (int c = 0; c < NCHUNK; c++) {
        const int buf = c & 1;
        const uint32_t bo = buf ? BUFO : 0;

        if (c + 1 < NCHUNK) {
            cpA(c + 1, buf ^ 1);
            cpB(c + 1, buf ^ 1);
            cp_commit();
        }

#pragma unroll
        for (int k16 = 0; k16 < 2; k16++) {
            const uint32_t kb = bo + k16 * 32;
            uint32_t Af[2][4];
            ldsm_x4(Af[0], aA0 + kb);
            ldsm_x4(Af[1], aA1 + kb);
            uint32_t Bf[8][2];
#pragma unroll
            for (int j = 0; j < 4; j++) {
                uint32_t t[4];
                ldsm_x4(t, aBhx[j] + kb);
                Bf[2 * j][0] = t[0]; Bf[2 * j][1] = t[1];
                Bf[2 * j + 1][0] = t[2]; Bf[2 * j + 1][1] = t[3];
            }
#pragma unroll
            for (int mf = 0; mf < 2; mf++)
#pragma unroll
                for (int nf = 0; nf < 8; nf++) mma16816(acc[mf][nf], Af[mf], Bf[nf]);
#pragma unroll
            for (int j = 0; j < 4; j++) {
                uint32_t t[4];
                ldsm_x4(t, aBlx[j] + kb);
                Bf[2 * j][0] = t[0]; Bf[2 * j][1] = t[1];
                Bf[2 * j + 1][0] = t[2]; Bf[2 * j + 1][1] = t[3];
            }
#pragma unroll
            for (int mf = 0; mf < 2; mf++)
#pragma unroll
                for (int nf = 0; nf < 8; nf++) mma16816(acc[mf][nf], Af[mf], Bf[nf]);
        }

        if (c + 1 < NCHUNK) cp_wait0();
        __syncthreads();
    }

    // ---- epilogue: bias + relu -> fp16 store ----
    const int er = lane >> 2, ec = (lane & 3) * 2;
    float2 bv[8];
#pragma unroll
    for (int nf = 0; nf < 8; nf++)
        bv[nf] = *(const float2*)(bias + nc0 + nf * 8 + ec);

#pragma unroll
    for (int mf = 0; mf < 2; mf++) {
#pragma unroll
        for (int half = 0; half < 2; half++) {
            int gr = brow + mr0 + mf * 16 + half * 8 + er;
            if (gr < M) {
                __half* op = Hout + (size_t)gr * HD + nc0 + ec;
#pragma unroll
                for (int nf = 0; nf < 8; nf++) {
                    float ox = fmaxf(acc[mf][nf][half * 2]     + bv[nf].x, 0.f);
                    float oy = fmaxf(acc[mf][nf][half * 2 + 1] + bv[nf].y, 0.f);
                    *(__half2*)(op + nf * 8) = __floats2half2_rn(ox, oy);
                }
            }
        }
    }
}

// out[n] = dot(h2[n,:], Wc) + bc; one warp per node
__global__ void classify_kernel(const __half* __restrict__ h, const float* __restrict__ Wc,
                                const float* __restrict__ bc, float* __restrict__ out, int M) {
    int t = blockIdx.x * blockDim.x + threadIdx.x;
    int n = t >> 5, lane = t & 31;
    if (n >= M) return;
    uint2 u = *(const uint2*)(h + (size_t)n * HD + lane * 4);
    float2 f0 = __half22float2(*(const __half2*)&u.x);
    float2 f1 = __half22float2(*(const __half2*)&u.y);
    float4 w = *(const float4*)(Wc + lane * 4);
    float s = f0.x * w.x + f0.y * w.y + f1.x * w.z + f1.y * w.w;
#pragma unroll
    for (int o = 16; o; o >>= 1) s += __shfl_xor_sync(0xffffffffu, s, o);
    if (lane == 0) out[n] = s + bc[0];
}

// ---------------- launch ----------------
extern "C" void kernel_launch(void* const* d_in, const int* in_sizes, int n_in,
                              void* d_out, int out_size) {
    const float* x  = (const float*)d_in[0];
    const int*   ei = (const int*)d_in[1];
    const int*   et = (const int*)d_in[2];
    const float* W1 = (const float*)d_in[3];
    const float* r1 = (const float*)d_in[4];
    const float* b1 = (const float*)d_in[5];
    const float* W2 = (const float*)d_in[6];
    const float* r2 = (const float*)d_in[7];
    const float* b2 = (const float*)d_in[8];
    const float* Wc = (const float*)d_in[9];
    const float* bc = (const float*)d_in[10];

    int M = in_sizes[0] / HD;    // 50000
    int E = in_sizes[1] / 2;     // 500000
    const int* src = ei;
    const int* dst = ei + E;

    __half *aggh, *xh, *h1, *h2;
    int *cnt, *off, *cur, *bsum, *esrc;
    __half *Bh1, *Bl1, *Bh2, *Bl2;
    cudaGetSymbolAddress((void**)&aggh, g_aggh);
    cudaGetSymbolAddress((void**)&cnt, g_cnt);
    cudaGetSymbolAddress((void**)&off, g_off);
    cudaGetSymbolAddress((void**)&cur, g_cur);
    cudaGetSymbolAddress((void**)&bsum, g_bsum);
    cudaGetSymbolAddress((void**)&esrc, g_esrc);
    cudaGetSymbolAddress((void**)&xh, g_xh);
    cudaGetSymbolAddress((void**)&h1, g_h1);
    cudaGetSymbolAddress((void**)&h2, g_h2);
    cudaGetSymbolAddress((void**)&Bh1, g_Bh1);
    cudaGetSymbolAddress((void**)&Bl1, g_Bl1);
    cudaGetSymbolAddress((void**)&Bh2, g_Bh2);
    cudaGetSymbolAddress((void**)&Bl2, g_Bl2);

    int nk = M * RR;
    int nb = (nk + 1023) / 1024;
    int mblocks = (M + 127) / 128;                // 391
    int eblocks = (E + 255) / 256;
    int pblocks = (128 * KTOT + 255) / 256;
    int ablocks = (M * 32 + 255) / 256;
    int xblocks = (M * HD / 4 + 255) / 256;

    // weight + feature prep (static per call)
    prep_kernel<<<pblocks, 256>>>(r1, W1, Bh1, Bl1);
    prep_kernel<<<pblocks, 256>>>(r2, W2, Bh2, Bl2);
    tohalf_kernel<<<xblocks, 256>>>(x, xh, M * HD);

    // ---- CSR build (shared by both layers) ----
    cudaMemsetAsync(cnt, 0, nk * sizeof(int));
    count_kernel<<<eblocks, 256>>>(dst, et, cnt, E);
    scan1_kernel<<<nb, 256>>>(cnt, bsum, nk);
    scan2_kernel<<<1, 512>>>(bsum, nb);
    scan3_kernel<<<nb, 256>>>(cnt, bsum, off, cur, nk);
    place_kernel<<<eblocks, 256>>>(src, dst, et, cur, esrc, E);

    // ---- layer 1 ----
    agg_kernel<<<ablocks, 256>>>(xh, esrc, off, cur, aggh, M);
    rgcn_mma<<<mblocks, 256>>>(xh, aggh, Bh1, Bl1, b1, h1, M);

    // ---- layer 2 ----
    agg_kernel<<<ablocks, 256>>>(h1, esrc, off, cur, aggh, M);
    rgcn_mma<<<mblocks, 256>>>(h1, aggh, Bh2, Bl2, b2, h2, M);

    // ---- classifier ----
    classify_kernel<<<((M * 32) + 255) / 256, 256>>>(h2, Wc, bc, (float*)d_out, M);
}

// round 11
// speedup vs baseline: 1.8122x; 1.2551x over previous
#include <cuda_runtime.h>
#include <cuda_fp16.h>
#include <cstdint>

#define HD   128
#define RR   8
#define NMAX 50000
#define EMAX 500000
#define NK   (NMAX * RR)        // 400000 bins
#define KTOT (HD + RR * HD)     // 1152
#define NCHUNK 36               // 1152 / 32
#define AST  40                 // smem row stride (fp16 elems): 32 + 8 pad

// ---------------- scratch (static device globals; no allocation) ----------------
__device__ __half g_aggh[(size_t)NMAX * RR * HD];   // [N,8,128] fp16, mean applied
__device__ int   g_cnt[NK];
__device__ int   g_off[NK];
__device__ int   g_cur[NK];
__device__ int   g_bsum[512];
__device__ int   g_esrc[EMAX];
__device__ __half g_xh[(size_t)NMAX * HD];
__device__ __half g_h1[(size_t)NMAX * HD];
__device__ __half g_h2[(size_t)NMAX * HD];
__device__ __half g_B1[128 * KTOT];                 // B^T fp16: [n][k]
__device__ __half g_B2[128 * KTOT];

// ---------------- mma.sync / ldmatrix / cp.async helpers (base PTX, sm_80+) -----
__device__ __forceinline__ uint32_t smem_u32(const void* p) {
    return (uint32_t)__cvta_generic_to_shared(p);
}
__device__ __forceinline__ void ldsm_x4(uint32_t* r, uint32_t addr) {
    asm volatile("ldmatrix.sync.aligned.m8n8.x4.shared.b16 {%0,%1,%2,%3}, [%4];"
                 : "=r"(r[0]), "=r"(r[1]), "=r"(r[2]), "=r"(r[3]) : "r"(addr));
}
__device__ __forceinline__ void mma16816(float* d, const uint32_t* a, const uint32_t* b) {
    asm volatile(
        "mma.sync.aligned.m16n8k16.row.col.f32.f16.f16.f32 "
        "{%0,%1,%2,%3}, {%4,%5,%6,%7}, {%8,%9}, {%0,%1,%2,%3};"
        : "+f"(d[0]), "+f"(d[1]), "+f"(d[2]), "+f"(d[3])
        : "r"(a[0]), "r"(a[1]), "r"(a[2]), "r"(a[3]), "r"(b[0]), "r"(b[1]));
}
__device__ __forceinline__ void cp_async16(uint32_t smem_dst, const void* gptr) {
    asm volatile("cp.async.cg.shared.global [%0], [%1], 16;"
                 :: "r"(smem_dst), "l"(gptr));
}
__device__ __forceinline__ void cp_commit() { asm volatile("cp.async.commit_group;"); }
__device__ __forceinline__ void cp_wait0()  { asm volatile("cp.async.wait_group 0;"); }

// ---------------- CSR build: count -> scan -> place ----------------
__global__ void count_kernel(const int* __restrict__ dst, const int* __restrict__ et,
                             int* cnt, int E) {
    int e = blockIdx.x * blockDim.x + threadIdx.x;
    if (e < E) atomicAdd(&cnt[dst[e] * RR + et[e]], 1);
}

__global__ void scan1_kernel(const int* __restrict__ cnt, int* bsum, int nk) {
    __shared__ int sh[256];
    int b = blockIdx.x, t = threadIdx.x;
    int base = b * 1024 + t * 4;
    int s = 0;
    if (base + 3 < nk) {
        int4 v = *(const int4*)(cnt + base);
        s = v.x + v.y + v.z + v.w;
    } else {
        for (int j = 0; j < 4; j++) if (base + j < nk) s += cnt[base + j];
    }
    sh[t] = s; __syncthreads();
    for (int o = 128; o; o >>= 1) { if (t < o) sh[t] += sh[t + o]; __syncthreads(); }
    if (t == 0) bsum[b] = sh[0];
}

__global__ void scan2_kernel(int* bsum, int nb) {
    __shared__ int sh[512];
    int t = threadIdx.x;
    int v = (t < nb) ? bsum[t] : 0;
    sh[t] = v; __syncthreads();
    for (int o = 1; o < 512; o <<= 1) {
        int add = (t >= o) ? sh[t - o] : 0;
        __syncthreads();
        sh[t] += add;
        __syncthreads();
    }
    if (t < nb) bsum[t] = sh[t] - v;   // exclusive
}

__global__ void scan3_kernel(const int* __restrict__ cnt, const int* __restrict__ bsum,
                             int* off, int* cur, int nk) {
    __shared__ int sh[256];
    int b = blockIdx.x, t = threadIdx.x;
    int base = b * 1024 + t * 4;
    int v[4] = {0, 0, 0, 0};
    if (base + 3 < nk) {
        int4 q = *(const int4*)(cnt + base);
        v[0] = q.x; v[1] = q.y; v[2] = q.z; v[3] = q.w;
    } else {
        for (int j = 0; j < 4; j++) if (base + j < nk) v[j] = cnt[base + j];
    }
    int ts = v[0] + v[1] + v[2] + v[3];
    sh[t] = ts; __syncthreads();
    for (int o = 1; o < 256; o <<= 1) {
        int add = (t >= o) ? sh[t - o] : 0;
        __syncthreads();
        sh[t] += add;
        __syncthreads();
    }
    int excl = sh[t] - ts + bsum[b];
    int o0 = excl, o1 = o0 + v[0], o2 = o1 + v[1], o3 = o2 + v[2];
    if (base + 3 < nk) {
        *(int4*)(off + base) = make_int4(o0, o1, o2, o3);
        *(int4*)(cur + base) = make_int4(o0, o1, o2, o3);
    } else {
        int oo[4] = {o0, o1, o2, o3};
        for (int j = 0; j < 4; j++)
            if (base + j < nk) { off[base + j] = oo[j]; cur[base + j] = oo[j]; }
    }
}

__global__ void place_kernel(const int* __restrict__ src, const int* __restrict__ dst,
                             const int* __restrict__ et, int* cur, int* esrc, int E) {
    int e = blockIdx.x * blockDim.x + threadIdx.x;
    if (e >= E) return;
    int key = dst[e] * RR + et[e];
    int pos = atomicAdd(&cur[key], 1);
    esrc[pos] = src[e];
}

// ---------------- fp32 -> fp16 convert ----------------
__global__ void tohalf_kernel(const float* __restrict__ in, __half* __restrict__ out, int n) {
    int t = (blockIdx.x * blockDim.x + threadIdx.x) * 4;
    if (t + 3 >= n) {
        for (int j = 0; j < 4 && t + j < n; j++) out[t + j] = __float2half(in[t + j]);
        return;
    }
    float4 v = *(const float4*)(in + t);
    __half2 a = __floats2half2_rn(v.x, v.y), b = __floats2half2_rn(v.z, v.w);
    *(uint2*)(out + t) = make_uint2(*(uint32_t*)&a, *(uint32_t*)&b);
}

// ---------------- aggregation: warp per dst node, fp16 in/out, mean applied ------
__global__ void agg_kernel(const __half* __restrict__ feat, const int* __restrict__ esrc,
                           const int* __restrict__ off, const int* __restrict__ cur,
                           __half* __restrict__ agg, int M) {
    int w = (blockIdx.x * blockDim.x + threadIdx.x) >> 5;
    int lane = threadIdx.x & 31;
    if (w >= M) return;
#pragma unroll
    for (int rel = 0; rel < RR; rel++) {
        int key = w * RR + rel;
        int s0 = off[key], s1 = cur[key];
        size_t ob = (size_t)w * (RR * HD) + rel * HD + lane * 4;
        if (s0 >= s1) {
            *(uint2*)(agg + ob) = make_uint2(0u, 0u);
            continue;
        }
        float a0 = 0.f, a1 = 0.f, a2 = 0.f, a3 = 0.f;
        int snext = esrc[s0];
        for (int e = s0; e < s1; e++) {
            int sc = snext;
            if (e + 1 < s1) snext = esrc[e + 1];
            uint2 u = *(const uint2*)(feat + (size_t)sc * HD + lane * 4);
            float2 f0 = __half22float2(*(const __half2*)&u.x);
            float2 f1 = __half22float2(*(const __half2*)&u.y);
            a0 += f0.x; a1 += f0.y; a2 += f1.x; a3 += f1.y;
        }
        float s = 1.0f / (float)(s1 - s0);
        __half2 h0 = __floats2half2_rn(a0 * s, a1 * s);
        __half2 h1 = __floats2half2_rn(a2 * s, a3 * s);
        *(uint2*)(agg + ob) = make_uint2(*(uint32_t*)&h0, *(uint32_t*)&h1);
    }
}

// weight prep: B^T[n][k] fp16.  k<128 -> root[k][n], else W[(k-128)][n]
__global__ void prep_kernel(const float* __restrict__ root, const float* __restrict__ W,
                            __half* B) {
    int t = blockIdx.x * blockDim.x + threadIdx.x;
    if (t >= 128 * KTOT) return;
    int n = t / KTOT, k = t % KTOT;
    float v = (k < HD) ? root[k * HD + n] : W[(size_t)(k - HD) * HD + n];
    B[t] = __float2half(v);
}

// ---------------- fp16 1-term mma.sync GEMM, all cp.async ----------------
// out_fp16 = relu( [Xh | Aggh] @ B + bias )
__global__ __launch_bounds__(256, 2) void rgcn_mma(
    const __half* __restrict__ Xh, const __half* __restrict__ Aggh,
    const __half* __restrict__ B,
    const float* __restrict__ bias, __half* __restrict__ Hout, int M) {

    __shared__ __half A_s[2][128][AST];
    __shared__ __half B_s[2][128][AST];

    const int tid = threadIdx.x;
    const int wid = tid >> 5;
    const int lane = tid & 31;
    const int brow = blockIdx.x * 128;

    // warp tile: 4 (m) x 2 (n); each warp 32 rows x 64 cols
    const int warp_m = wid & 3, warp_n = wid >> 2;
    const int mr0 = warp_m * 32, nc0 = warp_n * 64;

    const int alr = lane & 15, alc = (lane >> 4) << 3;
    const uint32_t aA0 = smem_u32(&A_s[0][mr0 + alr][alc]);
    const uint32_t aA1 = smem_u32(&A_s[0][mr0 + 16 + alr][alc]);
    const int blr = (lane & 7) + ((lane >> 4) << 3);
    const int blc = ((lane >> 3) & 1) << 3;
    uint32_t aBx[4];
#pragma unroll
    for (int j = 0; j < 4; j++)
        aBx[j] = smem_u32(&B_s[0][nc0 + blr + j * 16][blc]);
    const uint32_t BUFO = 128 * AST * 2;    // bytes per stage

    float acc[2][8][4];
#pragma unroll
    for (int i = 0; i < 2; i++)
#pragma unroll
        for (int j = 0; j < 8; j++)
#pragma unroll
            for (int q = 0; q < 4; q++) acc[i][j][q] = 0.f;

    // staging: thread -> (row 0..127, 16-elem k half)
    const int arow = tid >> 1;
    const int aks  = (tid & 1) << 4;
    int g = brow + arow;
    if (g >= M) g = M - 1;                  // clamp; garbage rows masked at store

    auto cpA = [&](int c, int buf) {
        const __half* s = (c < 4)
            ? Xh + (size_t)g * HD + c * 32 + aks
            : Aggh + (size_t)g * (RR * HD) + (c - 4) * 32 + aks;
        uint32_t d = smem_u32(&A_s[buf][arow][aks]);
        cp_async16(d, s);
        cp_async16(d + 16, s + 8);
    };
    auto cpB = [&](int c, int buf) {
        const __half* b = B + (size_t)arow * KTOT + c * 32 + aks;
        uint32_t d = smem_u32(&B_s[buf][arow][aks]);
        cp_async16(d, b);
        cp_async16(d + 16, b + 8);
    };

    // ---- prologue ----
    cpA(0, 0);
    cpB(0, 0);
    cp_commit();
    cp_wait0();
    __syncthreads();

    // ---- mainloop: cp.async + ldsm + HMMA only ----
    for (int c = 0; c < NCHUNK; c++) {
        const int buf = c & 1;
        const uint32_t bo = buf ? BUFO : 0;

        if (c + 1 < NCHUNK) {
            cpA(c + 1, buf ^ 1);
            cpB(c + 1, buf ^ 1);
            cp_commit();
        }

#pragma unroll
        for (int k16 = 0; k16 < 2; k16++) {
            const uint32_t kb = bo + k16 * 32;
            uint32_t Af[2][4];
            ldsm_x4(Af[0], aA0 + kb);
            ldsm_x4(Af[1], aA1 + kb);
            uint32_t Bf[8][2];
#pragma unroll
            for (int j = 0; j < 4; j++) {
                uint32_t t[4];
                ldsm_x4(t, aBx[j] + kb);
                Bf[2 * j][0] = t[0]; Bf[2 * j][1] = t[1];
                Bf[2 * j + 1][0] = t[2]; Bf[2 * j + 1][1] = t[3];
            }
#pragma unroll
            for (int mf = 0; mf < 2; mf++)
#pragma unroll
                for (int nf = 0; nf < 8; nf++) mma16816(acc[mf][nf], Af[mf], Bf[nf]);
        }

        if (c + 1 < NCHUNK) cp_wait0();
        __syncthreads();
    }

    // ---- epilogue: bias + relu -> fp16 store ----
    const int er = lane >> 2, ec = (lane & 3) * 2;
    float2 bv[8];
#pragma unroll
    for (int nf = 0; nf < 8; nf++)
        bv[nf] = *(const float2*)(bias + nc0 + nf * 8 + ec);

#pragma unroll
    for (int mf = 0; mf < 2; mf++) {
#pragma unroll
        for (int half = 0; half < 2; half++) {
            int gr = brow + mr0 + mf * 16 + half * 8 + er;
            if (gr < M) {
                __half* op = Hout + (size_t)gr * HD + nc0 + ec;
#pragma unroll
                for (int nf = 0; nf < 8; nf++) {
                    float ox = fmaxf(acc[mf][nf][half * 2]     + bv[nf].x, 0.f);
                    float oy = fmaxf(acc[mf][nf][half * 2 + 1] + bv[nf].y, 0.f);
                    *(__half2*)(op + nf * 8) = __floats2half2_rn(ox, oy);
                }
            }
        }
    }
}

// out[n] = dot(h2[n,:], Wc) + bc; one warp per node
__global__ void classify_kernel(const __half* __restrict__ h, const float* __restrict__ Wc,
                                const float* __restrict__ bc, float* __restrict__ out, int M) {
    int t = blockIdx.x * blockDim.x + threadIdx.x;
    int n = t >> 5, lane = t & 31;
    if (n >= M) return;
    uint2 u = *(const uint2*)(h + (size_t)n * HD + lane * 4);
    float2 f0 = __half22float2(*(const __half2*)&u.x);
    float2 f1 = __half22float2(*(const __half2*)&u.y);
    float4 w = *(const float4*)(Wc + lane * 4);
    float s = f0.x * w.x + f0.y * w.y + f1.x * w.z + f1.y * w.w;
#pragma unroll
    for (int o = 16; o; o >>= 1) s += __shfl_xor_sync(0xffffffffu, s, o);
    if (lane == 0) out[n] = s + bc[0];
}

// ---------------- launch ----------------
extern "C" void kernel_launch(void* const* d_in, const int* in_sizes, int n_in,
                              void* d_out, int out_size) {
    const float* x  = (const float*)d_in[0];
    const int*   ei = (const int*)d_in[1];
    const int*   et = (const int*)d_in[2];
    const float* W1 = (const float*)d_in[3];
    const float* r1 = (const float*)d_in[4];
    const float* b1 = (const float*)d_in[5];
    const float* W2 = (const float*)d_in[6];
    const float* r2 = (const float*)d_in[7];
    const float* b2 = (const float*)d_in[8];
    const float* Wc = (const float*)d_in[9];
    const float* bc = (const float*)d_in[10];

    int M = in_sizes[0] / HD;    // 50000
    int E = in_sizes[1] / 2;     // 500000
    const int* src = ei;
    const int* dst = ei + E;

    __half *aggh, *xh, *h1, *h2;
    int *cnt, *off, *cur, *bsum, *esrc;
    __half *B1, *B2;
    cudaGetSymbolAddress((void**)&aggh, g_aggh);
    cudaGetSymbolAddress((void**)&cnt, g_cnt);
    cudaGetSymbolAddress((void**)&off, g_off);
    cudaGetSymbolAddress((void**)&cur, g_cur);
    cudaGetSymbolAddress((void**)&bsum, g_bsum);
    cudaGetSymbolAddress((void**)&esrc, g_esrc);
    cudaGetSymbolAddress((void**)&xh, g_xh);
    cudaGetSymbolAddress((void**)&h1, g_h1);
    cudaGetSymbolAddress((void**)&h2, g_h2);
    cudaGetSymbolAddress((void**)&B1, g_B1);
    cudaGetSymbolAddress((void**)&B2, g_B2);

    int nk = M * RR;
    int nb = (nk + 1023) / 1024;
    int mblocks = (M + 127) / 128;                // 391
    int eblocks = (E + 255) / 256;
    int pblocks = (128 * KTOT + 255) / 256;
    int ablocks = (M * 32 + 255) / 256;
    int xblocks = (M * HD / 4 + 255) / 256;

    // weight + feature prep (static per call)
    prep_kernel<<<pblocks, 256>>>(r1, W1, B1);
    prep_kernel<<<pblocks, 256>>>(r2, W2, B2);
    tohalf_kernel<<<xblocks, 256>>>(x, xh, M * HD);

    // ---- CSR build (shared by both layers) ----
    cudaMemsetAsync(cnt, 0, nk * sizeof(int));
    count_kernel<<<eblocks, 256>>>(dst, et, cnt, E);
    scan1_kernel<<<nb, 256>>>(cnt, bsum, nk);
    scan2_kernel<<<1, 512>>>(bsum, nb);
    scan3_kernel<<<nb, 256>>>(cnt, bsum, off, cur, nk);
    place_kernel<<<eblocks, 256>>>(src, dst, et, cur, esrc, E);

    // ---- layer 1 ----
    agg_kernel<<<ablocks, 256>>>(xh, esrc, off, cur, aggh, M);
    rgcn_mma<<<mblocks, 256>>>(xh, aggh, B1, b1, h1, M);

    // ---- layer 2 ----
    agg_kernel<<<ablocks, 256>>>(h1, esrc, off, cur, aggh, M);
    rgcn_mma<<<mblocks, 256>>>(h1, aggh, B2, b2, h2, M);

    // ---- classifier ----
    classify_kernel<<<((M * 32) + 255) / 256, 256>>>(h2, Wc, bc, (float*)d_out, M);
}

// round 12
// speedup vs baseline: 1.9935x; 1.1001x over previous
#include <cuda_runtime.h>
#include <cuda_fp16.h>
#include <cstdint>

#define HD   128
#define RR   8
#define NMAX 50000
#define EMAX 500000
#define NK   (NMAX * RR)        // 400000 bins
#define KTOT (HD + RR * HD)     // 1152
#define NCHUNK 36               // 1152 / 32
#define AST  40                 // smem row stride (fp16 elems): 32 + 8 pad

#define ABYTES (128 * AST * 2)          // 10240 bytes per A stage
#define STAGEB (2 * ABYTES)             // A + B per stage = 20480
#define NSTAGE 4
#define SM_WC   (NSTAGE * STAGEB)       // 81920: Wc (128 floats)
#define SM_RED  (SM_WC + 512)           // reduce buffer (128*2 floats)
#define SMEMSZ  (SM_RED + 1024)         // 83456 bytes

// ---------------- scratch (static device globals; no allocation) ----------------
__device__ __half g_aggh[(size_t)NMAX * RR * HD];   // [N,8,128] fp16, mean applied
__device__ int   g_cnt[NK];
__device__ int   g_off[NK];
__device__ int   g_cur[NK];
__device__ int   g_bsum[512];
__device__ int   g_esrc[EMAX];
__device__ __half g_xh[(size_t)NMAX * HD];
__device__ __half g_h1[(size_t)NMAX * HD];
__device__ __half g_B1[128 * KTOT];                 // B^T fp16: [n][k]
__device__ __half g_B2[128 * KTOT];

// ---------------- mma.sync / ldmatrix / cp.async helpers (base PTX, sm_80+) -----
__device__ __forceinline__ uint32_t smem_u32(const void* p) {
    return (uint32_t)__cvta_generic_to_shared(p);
}
__device__ __forceinline__ void ldsm_x4(uint32_t* r, uint32_t addr) {
    asm volatile("ldmatrix.sync.aligned.m8n8.x4.shared.b16 {%0,%1,%2,%3}, [%4];"
                 : "=r"(r[0]), "=r"(r[1]), "=r"(r[2]), "=r"(r[3]) : "r"(addr));
}
__device__ __forceinline__ void mma16816(float* d, const uint32_t* a, const uint32_t* b) {
    asm volatile(
        "mma.sync.aligned.m16n8k16.row.col.f32.f16.f16.f32 "
        "{%0,%1,%2,%3}, {%4,%5,%6,%7}, {%8,%9}, {%0,%1,%2,%3};"
        : "+f"(d[0]), "+f"(d[1]), "+f"(d[2]), "+f"(d[3])
        : "r"(a[0]), "r"(a[1]), "r"(a[2]), "r"(a[3]), "r"(b[0]), "r"(b[1]));
}
__device__ __forceinline__ void cp_async16(uint32_t smem_dst, const void* gptr) {
    asm volatile("cp.async.cg.shared.global [%0], [%1], 16;"
                 :: "r"(smem_dst), "l"(gptr));
}
__device__ __forceinline__ void cp_commit() { asm volatile("cp.async.commit_group;"); }
__device__ __forceinline__ void cp_wait0()  { asm volatile("cp.async.wait_group 0;"); }
__device__ __forceinline__ void cp_wait1()  { asm volatile("cp.async.wait_group 1;"); }
__device__ __forceinline__ void cp_wait2()  { asm volatile("cp.async.wait_group 2;"); }

// ---------------- CSR build: count -> scan -> place ----------------
__global__ void count_kernel(const int* __restrict__ dst, const int* __restrict__ et,
                             int* cnt, int E) {
    int e = blockIdx.x * blockDim.x + threadIdx.x;
    if (e < E) atomicAdd(&cnt[dst[e] * RR + et[e]], 1);
}

__global__ void scan1_kernel(const int* __restrict__ cnt, int* bsum, int nk) {
    __shared__ int sh[256];
    int b = blockIdx.x, t = threadIdx.x;
    int base = b * 1024 + t * 4;
    int s = 0;
    if (base + 3 < nk) {
        int4 v = *(const int4*)(cnt + base);
        s = v.x + v.y + v.z + v.w;
    } else {
        for (int j = 0; j < 4; j++) if (base + j < nk) s += cnt[base + j];
    }
    sh[t] = s; __syncthreads();
    for (int o = 128; o; o >>= 1) { if (t < o) sh[t] += sh[t + o]; __syncthreads(); }
    if (t == 0) bsum[b] = sh[0];
}

__global__ void scan2_kernel(int* bsum, int nb) {
    __shared__ int sh[512];
    int t = threadIdx.x;
    int v = (t < nb) ? bsum[t] : 0;
    sh[t] = v; __syncthreads();
    for (int o = 1; o < 512; o <<= 1) {
        int add = (t >= o) ? sh[t - o] : 0;
        __syncthreads();
        sh[t] += add;
        __syncthreads();
    }
    if (t < nb) bsum[t] = sh[t] - v;   // exclusive
}

__global__ void scan3_kernel(const int* __restrict__ cnt, const int* __restrict__ bsum,
                             int* off, int* cur, int nk) {
    __shared__ int sh[256];
    int b = blockIdx.x, t = threadIdx.x;
    int base = b * 1024 + t * 4;
    int v[4] = {0, 0, 0, 0};
    if (base + 3 < nk) {
        int4 q = *(const int4*)(cnt + base);
        v[0] = q.x; v[1] = q.y; v[2] = q.z; v[3] = q.w;
    } else {
        for (int j = 0; j < 4; j++) if (base + j < nk) v[j] = cnt[base + j];
    }
    int ts = v[0] + v[1] + v[2] + v[3];
    sh[t] = ts; __syncthreads();
    for (int o = 1; o < 256; o <<= 1) {
        int add = (t >= o) ? sh[t - o] : 0;
        __syncthreads();
        sh[t] += add;
        __syncthreads();
    }
    int excl = sh[t] - ts + bsum[b];
    int o0 = excl, o1 = o0 + v[0], o2 = o1 + v[1], o3 = o2 + v[2];
    if (base + 3 < nk) {
        *(int4*)(off + base) = make_int4(o0, o1, o2, o3);
        *(int4*)(cur + base) = make_int4(o0, o1, o2, o3);
    } else {
        int oo[4] = {o0, o1, o2, o3};
        for (int j = 0; j < 4; j++)
            if (base + j < nk) { off[base + j] = oo[j]; cur[base + j] = oo[j]; }
    }
}

__global__ void place_kernel(const int* __restrict__ src, const int* __restrict__ dst,
                             const int* __restrict__ et, int* cur, int* esrc, int E) {
    int e = blockIdx.x * blockDim.x + threadIdx.x;
    if (e >= E) return;
    int key = dst[e] * RR + et[e];
    int pos = atomicAdd(&cur[key], 1);
    esrc[pos] = src[e];
}

// ---------------- fp32 -> fp16 convert ----------------
__global__ void tohalf_kernel(const float* __restrict__ in, __half* __restrict__ out, int n) {
    int t = (blockIdx.x * blockDim.x + threadIdx.x) * 4;
    if (t + 3 >= n) {
        for (int j = 0; j < 4 && t + j < n; j++) out[t + j] = __float2half(in[t + j]);
        return;
    }
    float4 v = *(const float4*)(in + t);
    __half2 a = __floats2half2_rn(v.x, v.y), b = __floats2half2_rn(v.z, v.w);
    *(uint2*)(out + t) = make_uint2(*(uint32_t*)&a, *(uint32_t*)&b);
}

// ---------------- aggregation: warp per dst node, fp16 in/out, mean applied ------
__global__ void agg_kernel(const __half* __restrict__ feat, const int* __restrict__ esrc,
                           const int* __restrict__ off, const int* __restrict__ cur,
                           __half* __restrict__ agg, int M) {
    int w = (blockIdx.x * blockDim.x + threadIdx.x) >> 5;
    int lane = threadIdx.x & 31;
    if (w >= M) return;
#pragma unroll
    for (int rel = 0; rel < RR; rel++) {
        int key = w * RR + rel;
        int s0 = off[key], s1 = cur[key];
        size_t ob = (size_t)w * (RR * HD) + rel * HD + lane * 4;
        if (s0 >= s1) {
            *(uint2*)(agg + ob) = make_uint2(0u, 0u);
            continue;
        }
        float a0 = 0.f, a1 = 0.f, a2 = 0.f, a3 = 0.f;
        int snext = esrc[s0];
        for (int e = s0; e < s1; e++) {
            int sc = snext;
            if (e + 1 < s1) snext = esrc[e + 1];
            uint2 u = *(const uint2*)(feat + (size_t)sc * HD + lane * 4);
            float2 f0 = __half22float2(*(const __half2*)&u.x);
            float2 f1 = __half22float2(*(const __half2*)&u.y);
            a0 += f0.x; a1 += f0.y; a2 += f1.x; a3 += f1.y;
        }
        float s = 1.0f / (float)(s1 - s0);
        __half2 h0 = __floats2half2_rn(a0 * s, a1 * s);
        __half2 h1 = __floats2half2_rn(a2 * s, a3 * s);
        *(uint2*)(agg + ob) = make_uint2(*(uint32_t*)&h0, *(uint32_t*)&h1);
    }
}

// weight prep: B^T[n][k] fp16.  k<128 -> root[k][n], else W[(k-128)][n]
__global__ void prep_kernel(const float* __restrict__ root, const float* __restrict__ W,
                            __half* B) {
    int t = blockIdx.x * blockDim.x + threadIdx.x;
    if (t >= 128 * KTOT) return;
    int n = t / KTOT, k = t % KTOT;
    float v = (k < HD) ? root[k * HD + n] : W[(size_t)(k - HD) * HD + n];
    B[t] = __float2half(v);
}

// ---------------- fp16 mma.sync GEMM, 4-stage cp.async pipeline ----------------
// relu( [Xh | Aggh] @ B + bias ) -> Hout fp16, OR (Wc != null) -> out[row] = dot+bc
__global__ __launch_bounds__(256, 2) void rgcn_mma(
    const __half* __restrict__ Xh, const __half* __restrict__ Aggh,
    const __half* __restrict__ B,
    const float* __restrict__ bias, __half* __restrict__ Hout, int M,
    const float* __restrict__ Wc, const float* __restrict__ bc,
    float* __restrict__ out) {

    extern __shared__ char smem[];
    const uint32_t sb = smem_u32(smem);
    float* Wcs = (float*)(smem + SM_WC);
    float* red = (float*)(smem + SM_RED);

    const int tid = threadIdx.x;
    const int wid = tid >> 5;
    const int lane = tid & 31;
    const int brow = blockIdx.x * 128;
    const bool fused = (Wc != nullptr);

    if (fused && tid < 128) Wcs[tid] = Wc[tid];

    // warp tile: 4 (m) x 2 (n); each warp 32 rows x 64 cols
    const int warp_m = wid & 3, warp_n = wid >> 2;
    const int mr0 = warp_m * 32, nc0 = warp_n * 64;

    const int alr = lane & 15, alc = (lane >> 4) << 3;
    const uint32_t aA0 = sb + (mr0 + alr) * (AST * 2) + alc * 2;
    const uint32_t aA1 = sb + (mr0 + 16 + alr) * (AST * 2) + alc * 2;
    const int blr = (lane & 7) + ((lane >> 4) << 3);
    const int blc = ((lane >> 3) & 1) << 3;
    uint32_t aBx[4];
#pragma unroll
    for (int j = 0; j < 4; j++)
        aBx[j] = sb + ABYTES + (nc0 + blr + j * 16) * (AST * 2) + blc * 2;

    float acc[2][8][4];
#pragma unroll
    for (int i = 0; i < 2; i++)
#pragma unroll
        for (int j = 0; j < 8; j++)
#pragma unroll
            for (int q = 0; q < 4; q++) acc[i][j][q] = 0.f;

    // staging: thread -> (row 0..127, 16-elem k half)
    const int arow = tid >> 1;
    const int aks  = (tid & 1) << 4;
    int g = brow + arow;
    if (g >= M) g = M - 1;                  // clamp; garbage rows masked at store

    auto cpA = [&](int c, int st) {
        const __half* s = (c < 4)
            ? Xh + (size_t)g * HD + c * 32 + aks
            : Aggh + (size_t)g * (RR * HD) + (c - 4) * 32 + aks;
        uint32_t d = sb + st * STAGEB + arow * (AST * 2) + aks * 2;
        cp_async16(d, s);
        cp_async16(d + 16, s + 8);
    };
    auto cpB = [&](int c, int st) {
        const __half* b = B + (size_t)arow * KTOT + c * 32 + aks;
        uint32_t d = sb + st * STAGEB + ABYTES + arow * (AST * 2) + aks * 2;
        cp_async16(d, b);
        cp_async16(d + 16, b + 8);
    };

    // ---- prologue: stages 0,1,2 in flight ----
    cpA(0, 0); cpB(0, 0); cp_commit();
    cpA(1, 1); cpB(1, 1); cp_commit();
    cpA(2, 2); cpB(2, 2); cp_commit();

    // ---- mainloop ----
    for (int c = 0; c < NCHUNK; c++) {
        // ensure group c complete (groups c+1..c+2 may stay outstanding)
        if (c + 2 < NCHUNK)      cp_wait2();
        else if (c + 1 < NCHUNK) cp_wait1();
        else                     cp_wait0();
        __syncthreads();   // all warps done with chunk c-1; stage c visible

        if (c + 3 < NCHUNK) {
            cpA(c + 3, (c + 3) & 3);
            cpB(c + 3, (c + 3) & 3);
            cp_commit();
        }

        const uint32_t bo = (uint32_t)(c & 3) * STAGEB;
#pragma unroll
        for (int k16 = 0; k16 < 2; k16++) {
            const uint32_t kb = bo + k16 * 32;
            uint32_t Af[2][4];
            ldsm_x4(Af[0], aA0 + kb);
            ldsm_x4(Af[1], aA1 + kb);
            uint32_t Bf[8][2];
#pragma unroll
            for (int j = 0; j < 4; j++) {
                uint32_t t[4];
                ldsm_x4(t, aBx[j] + kb);
                Bf[2 * j][0] = t[0]; Bf[2 * j][1] = t[1];
                Bf[2 * j + 1][0] = t[2]; Bf[2 * j + 1][1] = t[3];
            }
#pragma unroll
            for (int mf = 0; mf < 2; mf++)
#pragma unroll
                for (int nf = 0; nf < 8; nf++) mma16816(acc[mf][nf], Af[mf], Bf[nf]);
        }
    }

    // ---- epilogue ----
    const int er = lane >> 2, ec = (lane & 3) * 2;
    float2 bv[8];
#pragma unroll
    for (int nf = 0; nf < 8; nf++)
        bv[nf] = *(const float2*)(bias + nc0 + nf * 8 + ec);

    if (!fused) {
        // relu -> fp16 store
#pragma unroll
        for (int mf = 0; mf < 2; mf++) {
#pragma unroll
            for (int half = 0; half < 2; half++) {
                int gr = brow + mr0 + mf * 16 + half * 8 + er;
                if (gr < M) {
                    __half* op = Hout + (size_t)gr * HD + nc0 + ec;
#pragma unroll
                    for (int nf = 0; nf < 8; nf++) {
                        float ox = fmaxf(acc[mf][nf][half * 2]     + bv[nf].x, 0.f);
                        float oy = fmaxf(acc[mf][nf][half * 2 + 1] + bv[nf].y, 0.f);
                        *(__half2*)(op + nf * 8) = __floats2half2_rn(ox, oy);
                    }
                }
            }
        }
    } else {
        // fused classifier: out[row] = dot(relu(row), Wc) + bc
        __syncthreads();   // Wcs visible (loaded at kernel start), reuse of smem region safe
#pragma unroll
        for (int mf = 0; mf < 2; mf++) {
#pragma unroll
            for (int half = 0; half < 2; half++) {
                int rl = mr0 + mf * 16 + half * 8 + er;   // local row 0..127
                float s = 0.f;
#pragma unroll
                for (int nf = 0; nf < 8; nf++) {
                    float ox = fmaxf(acc[mf][nf][half * 2]     + bv[nf].x, 0.f);
                    float oy = fmaxf(acc[mf][nf][half * 2 + 1] + bv[nf].y, 0.f);
                    s += ox * Wcs[nc0 + nf * 8 + ec] + oy * Wcs[nc0 + nf * 8 + ec + 1];
                }
                s += __shfl_xor_sync(0xffffffffu, s, 1);
                s += __shfl_xor_sync(0xffffffffu, s, 2);
                if ((lane & 3) == 0) red[rl * 2 + warp_n] = s;
            }
        }
        __syncthreads();
        if (tid < 128) {
            int gr = brow + tid;
            if (gr < M) out[gr] = red[tid * 2] + red[tid * 2 + 1] + bc[0];
        }
    }
}

// ---------------- launch ----------------
extern "C" void kernel_launch(void* const* d_in, const int* in_sizes, int n_in,
                              void* d_out, int out_size) {
    const float* x  = (const float*)d_in[0];
    const int*   ei = (const int*)d_in[1];
    const int*   et = (const int*)d_in[2];
    const float* W1 = (const float*)d_in[3];
    const float* r1 = (const float*)d_in[4];
    const float* b1 = (const float*)d_in[5];
    const float* W2 = (const float*)d_in[6];
    const float* r2 = (const float*)d_in[7];
    const float* b2 = (const float*)d_in[8];
    const float* Wc = (const float*)d_in[9];
    const float* bc = (const float*)d_in[10];

    int M = in_sizes[0] / HD;    // 50000
    int E = in_sizes[1] / 2;     // 500000
    const int* src = ei;
    const int* dst = ei + E;

    __half *aggh, *xh, *h1;
    int *cnt, *off, *cur, *bsum, *esrc;
    __half *B1, *B2;
    cudaGetSymbolAddress((void**)&aggh, g_aggh);
    cudaGetSymbolAddress((void**)&cnt, g_cnt);
    cudaGetSymbolAddress((void**)&off, g_off);
    cudaGetSymbolAddress((void**)&cur, g_cur);
    cudaGetSymbolAddress((void**)&bsum, g_bsum);
    cudaGetSymbolAddress((void**)&esrc, g_esrc);
    cudaGetSymbolAddress((void**)&xh, g_xh);
    cudaGetSymbolAddress((void**)&h1, g_h1);
    cudaGetSymbolAddress((void**)&B1, g_B1);
    cudaGetSymbolAddress((void**)&B2, g_B2);

    cudaFuncSetAttribute(rgcn_mma, cudaFuncAttributeMaxDynamicSharedMemorySize, SMEMSZ);

    int nk = M * RR;
    int nb = (nk + 1023) / 1024;
    int mblocks = (M + 127) / 128;                // 391
    int eblocks = (E + 255) / 256;
    int pblocks = (128 * KTOT + 255) / 256;
    int ablocks = (M * 32 + 255) / 256;
    int xblocks = (M * HD / 4 + 255) / 256;

    // weight + feature prep (static per call)
    prep_kernel<<<pblocks, 256>>>(r1, W1, B1);
    prep_kernel<<<pblocks, 256>>>(r2, W2, B2);
    tohalf_kernel<<<xblocks, 256>>>(x, xh, M * HD);

    // ---- CSR build (shared by both layers) ----
    cudaMemsetAsync(cnt, 0, nk * sizeof(int));
    count_kernel<<<eblocks, 256>>>(dst, et, cnt, E);
    scan1_kernel<<<nb, 256>>>(cnt, bsum, nk);
    scan2_kernel<<<1, 512>>>(bsum, nb);
    scan3_kernel<<<nb, 256>>>(cnt, bsum, off, cur, nk);
    place_kernel<<<eblocks, 256>>>(src, dst, et, cur, esrc, E);

    // ---- layer 1 ----
    agg_kernel<<<ablocks, 256>>>(xh, esrc, off, cur, aggh, M);
    rgcn_mma<<<mblocks, 256, SMEMSZ>>>(xh, aggh, B1, b1, h1, M,
                                       nullptr, nullptr, nullptr);

    // ---- layer 2 + fused classifier ----
    agg_kernel<<<ablocks, 256>>>(h1, esrc, off, cur, aggh, M);
    rgcn_mma<<<mblocks, 256, SMEMSZ>>>(h1, aggh, B2, b2, nullptr, M,
                                       Wc, bc, (float*)d_out);
}